// round 13
// baseline (speedup 1.0000x reference)
#include <cuda_runtime.h>
#include <cuda_bf16.h>
#include <math.h>
#include <stdint.h>

#define NN 8192
#define DD 128
#define ALPHAC 0.7f
#define BETAC  0.3f
#define LAMC   0.1f
#define SIMWIN 1e-4f

static __device__ float g_E[NN * DD];
static __device__ float g_V[NN * DD];
static __device__ float g_invnorm[NN];
static __device__ float g_invp[NN];
static __device__ float g_invn[NN];
static __device__ float g_any[NN];
static __device__ float g_SIM[(size_t)NN * NN];                // sim (fp32)
static __device__ __nv_bfloat16 g_Pb[(size_t)NN * NN];         // attn scores (bf16)
static __device__ unsigned char g_code[(size_t)NN * NN];       // region code 0..3
static __device__ __nv_bfloat16 g_Phi[(size_t)NN * NN];
static __device__ __nv_bfloat16 g_Plo[(size_t)NN * NN];
static __device__ unsigned int g_adjbits[NN * NN / 32];
static __device__ int g_flags[3 * 64 * 128];                   // [type][iblock][jchunk]
static __device__ __nv_bfloat16 g_Ehi[NN * DD], g_Elo[NN * DD];
static __device__ __nv_bfloat16 g_Qhi[NN * DD];
static __device__ __nv_bfloat16 g_Khi[NN * DD], g_Klo[NN * DD];
static __device__ __nv_bfloat16 g_Ethi[DD * NN], g_Etlo[DD * NN];
static __device__ __nv_bfloat16 g_Vthi[DD * NN], g_Vtlo[DD * NN];
static __device__ float g_pos[NN * DD];
static __device__ float g_neg[NN * DD];
static __device__ float g_bnd[NN * DD];
static __device__ float g_agg[NN * DD];

// ---------- baseline-PTX helpers ----------
__device__ __forceinline__ uint32_t smem_u32(const void* p) {
    uint32_t a;
    asm("{ .reg .u64 t; cvta.to.shared.u64 t, %1; cvt.u32.u64 %0, t; }" : "=r"(a) : "l"(p));
    return a;
}
__device__ __forceinline__ void ldsm4(uint32_t& r0, uint32_t& r1, uint32_t& r2, uint32_t& r3,
                                      uint32_t addr) {
    asm volatile("ldmatrix.sync.aligned.m8n8.x4.shared.b16 {%0,%1,%2,%3}, [%4];"
                 : "=r"(r0), "=r"(r1), "=r"(r2), "=r"(r3) : "r"(addr));
}
__device__ __forceinline__ void mma16816(float* c, uint32_t a0, uint32_t a1, uint32_t a2,
                                         uint32_t a3, uint32_t b0, uint32_t b1) {
    asm volatile(
        "mma.sync.aligned.m16n8k16.row.col.f32.bf16.bf16.f32 "
        "{%0,%1,%2,%3},{%4,%5,%6,%7},{%8,%9},{%0,%1,%2,%3};"
        : "+f"(c[0]), "+f"(c[1]), "+f"(c[2]), "+f"(c[3])
        : "r"(a0), "r"(a1), "r"(a2), "r"(a3), "r"(b0), "r"(b1));
}
__device__ __forceinline__ void cpa16(uint32_t saddr, const void* g) {
    asm volatile("cp.async.ca.shared.global [%0], [%1], 16;" :: "r"(saddr), "l"(g));
}
#define CP_COMMIT() asm volatile("cp.async.commit_group;" ::: "memory")
#define CP_WAIT0()  asm volatile("cp.async.wait_group 0;" ::: "memory")
#define CP_WAIT1()  asm volatile("cp.async.wait_group 1;" ::: "memory")

// ---------- small prep ----------
__global__ void init_kernel(const float* __restrict__ emb) {
    int idx = blockIdx.x * 256 + threadIdx.x;
    g_E[idx] = emb[idx];
}
__global__ void adjbits_kernel(const float* __restrict__ adj) {
    int w = blockIdx.x * 256 + threadIdx.x;
    size_t base = (size_t)w * 32;
    unsigned int bits = 0;
    #pragma unroll 8
    for (int b = 0; b < 32; b++) bits |= (adj[base + b] != 0.0f) ? (1u << b) : 0u;
    g_adjbits[w] = bits;
}
__global__ void zero_flags_kernel() {
    g_flags[blockIdx.x * 256 + threadIdx.x] = 0;
}
// norm + E hi/lo split (one warp per row)
__global__ void norm_kernel() {
    int gw = (blockIdx.x * blockDim.x + threadIdx.x) >> 5;
    if (gw >= NN) return;
    int lane = threadIdx.x & 31;
    size_t o = (size_t)gw * DD + lane * 4;
    float4 v = *(const float4*)(g_E + o);
    float s = v.x * v.x + v.y * v.y + v.z * v.z + v.w * v.w;
    #pragma unroll
    for (int of = 16; of > 0; of >>= 1) s += __shfl_xor_sync(0xFFFFFFFFu, s, of);
    if (lane == 0) g_invnorm[gw] = 1.0f / fmaxf(sqrtf(s), 1e-8f);
    __nv_bfloat16 hx = __float2bfloat16(v.x), hy = __float2bfloat16(v.y);
    __nv_bfloat16 hz = __float2bfloat16(v.z), hw = __float2bfloat16(v.w);
    *(__nv_bfloat162*)(g_Ehi + o)     = __halves2bfloat162(hx, hy);
    *(__nv_bfloat162*)(g_Ehi + o + 2) = __halves2bfloat162(hz, hw);
    *(__nv_bfloat162*)(g_Elo + o) = __halves2bfloat162(
        __float2bfloat16(v.x - __bfloat162float(hx)), __float2bfloat16(v.y - __bfloat162float(hy)));
    *(__nv_bfloat162*)(g_Elo + o + 2) = __halves2bfloat162(
        __float2bfloat16(v.z - __bfloat162float(hz)), __float2bfloat16(v.w - __bfloat162float(hw)));
}

// QKV + direct bf16 split writes
__global__ __launch_bounds__(128) void qkv_kernel(
    const float* __restrict__ wq, const float* __restrict__ bq,
    const float* __restrict__ wk, const float* __restrict__ bk,
    const float* __restrict__ wv, const float* __restrict__ bv)
{
    __shared__ float e[8][DD];
    int i0 = blockIdx.x * 8, t = threadIdx.x;
    #pragma unroll
    for (int r = 0; r < 8; r++) e[r][t] = g_E[(size_t)(i0 + r) * DD + t];
    __syncthreads();
    float q[8], k[8], v[8];
    float bqv = bq[t], bkv = bk[t], bvv = bv[t];
    #pragma unroll
    for (int r = 0; r < 8; r++) { q[r] = bqv; k[r] = bkv; v[r] = bvv; }
    #pragma unroll 4
    for (int kk = 0; kk < DD; kk++) {
        float a = wq[kk * DD + t], b = wk[kk * DD + t], c = wv[kk * DD + t];
        #pragma unroll
        for (int r = 0; r < 8; r++) {
            float x = e[r][kk];
            q[r] += x * a; k[r] += x * b; v[r] += x * c;
        }
    }
    #pragma unroll
    for (int r = 0; r < 8; r++) {
        size_t o = (size_t)(i0 + r) * DD + t;
        g_Qhi[o] = __float2bfloat16(q[r]);
        __nv_bfloat16 kh = __float2bfloat16(k[r]);
        g_Khi[o] = kh;
        g_Klo[o] = __float2bfloat16(k[r] - __bfloat162float(kh));
        g_V[o] = v[r];
    }
}

__global__ __launch_bounds__(256) void transpose_split_kernel() {
    __shared__ float te[32][33], tv[32][33];
    int jb = blockIdx.x * 32, db = blockIdx.y * 32;
    int tx = threadIdx.x & 31, ty = threadIdx.x >> 5;
    #pragma unroll
    for (int r = 0; r < 32; r += 8) {
        te[ty + r][tx] = g_E[(size_t)(jb + ty + r) * DD + db + tx];
        tv[ty + r][tx] = g_V[(size_t)(jb + ty + r) * DD + db + tx];
    }
    __syncthreads();
    #pragma unroll
    for (int r = 0; r < 32; r += 8) {
        size_t o = (size_t)(db + ty + r) * NN + jb + tx;
        float e = te[tx][ty + r];
        __nv_bfloat16 h = __float2bfloat16(e);
        g_Ethi[o] = h; g_Etlo[o] = __float2bfloat16(e - __bfloat162float(h));
        float v = tv[tx][ty + r];
        h = __float2bfloat16(v);
        g_Vthi[o] = h; g_Vtlo[o] = __float2bfloat16(v - __bfloat162float(h));
    }
}

// ---------- NT GEMM via mma.sync, merged split-passes ----------
// mode0: SIM = (E E^T)*invn_i*invn_j — A0·(B0,B1) merged + A1·B0, fp32 out
// mode1: P = (Q K^T)/sqrt(D) — A0·(B0,B1) merged (2-pass), bf16 out
__global__ __launch_bounds__(256) void simqk_mma(int mode) {
    extern __shared__ char smem[];
    const int STR = 136;
    const int PLH = 128 * STR;
    __nv_bfloat16* sm = (__nv_bfloat16*)smem;
    const __nv_bfloat16* gA0 = (mode == 0) ? g_Ehi : g_Qhi;
    const __nv_bfloat16* gB0 = (mode == 0) ? g_Ehi : g_Khi;
    const __nv_bfloat16* gB1 = (mode == 0) ? g_Elo : g_Klo;
    int tid = threadIdx.x;
    int m0 = blockIdx.y * 128, n0 = blockIdx.x * 128;

    for (int idx = tid; idx < 128 * 16; idx += 256) {
        int row = idx >> 4, cg = (idx & 15) * 8;
        size_t gm = (size_t)(m0 + row) * DD + cg;
        size_t gn = (size_t)(n0 + row) * DD + cg;
        int so = row * STR + cg;
        *(uint4*)(sm + 0 * PLH + so) = *(const uint4*)(gA0 + gm);
        if (mode == 0)
            *(uint4*)(sm + 1 * PLH + so) = *(const uint4*)(g_Elo + gm);
        *(uint4*)(sm + 2 * PLH + so) = *(const uint4*)(gB0 + gn);
        *(uint4*)(sm + 3 * PLH + so) = *(const uint4*)(gB1 + gn);
    }
    __syncthreads();

    int wid = tid >> 5, lane = tid & 31;
    int wm = wid & 3, wn = wid >> 2;
    uint32_t sb = smem_u32(smem);
    float acc[2][8][4];
    #pragma unroll
    for (int i = 0; i < 2; i++)
        #pragma unroll
        for (int j = 0; j < 8; j++)
            #pragma unroll
            for (int q = 0; q < 4; q++) acc[i][j][q] = 0.0f;

    int a_row = (lane & 15), a_kh = (lane >> 4) * 8;
    int b_row = (lane >> 4) * 8 + (lane & 7), b_kh = ((lane >> 3) & 1) * 8;

    #pragma unroll
    for (int ks = 0; ks < 8; ks++) {
        int k0 = ks * 16;
        uint32_t a[2][4];
        #pragma unroll
        for (int mt = 0; mt < 2; mt++) {
            int row = wm * 32 + mt * 16 + a_row;
            ldsm4(a[mt][0], a[mt][1], a[mt][2], a[mt][3],
                  sb + (uint32_t)(0 * PLH + row * STR + k0 + a_kh) * 2);
        }
        uint32_t b0[8][2], b1[8][2];
        #pragma unroll
        for (int np = 0; np < 4; np++) {
            int row = wn * 64 + np * 16 + b_row;
            ldsm4(b0[np * 2][0], b0[np * 2][1], b0[np * 2 + 1][0], b0[np * 2 + 1][1],
                  sb + (uint32_t)(2 * PLH + row * STR + k0 + b_kh) * 2);
            ldsm4(b1[np * 2][0], b1[np * 2][1], b1[np * 2 + 1][0], b1[np * 2 + 1][1],
                  sb + (uint32_t)(3 * PLH + row * STR + k0 + b_kh) * 2);
        }
        #pragma unroll
        for (int mt = 0; mt < 2; mt++)
            #pragma unroll
            for (int nt = 0; nt < 8; nt++) {
                mma16816(acc[mt][nt], a[mt][0], a[mt][1], a[mt][2], a[mt][3],
                         b0[nt][0], b0[nt][1]);
                mma16816(acc[mt][nt], a[mt][0], a[mt][1], a[mt][2], a[mt][3],
                         b1[nt][0], b1[nt][1]);
            }
    }
    if (mode == 0) {
        #pragma unroll
        for (int ks = 0; ks < 8; ks++) {
            int k0 = ks * 16;
            uint32_t a[2][4];
            #pragma unroll
            for (int mt = 0; mt < 2; mt++) {
                int row = wm * 32 + mt * 16 + a_row;
                ldsm4(a[mt][0], a[mt][1], a[mt][2], a[mt][3],
                      sb + (uint32_t)(1 * PLH + row * STR + k0 + a_kh) * 2);
            }
            uint32_t b0[8][2];
            #pragma unroll
            for (int np = 0; np < 4; np++) {
                int row = wn * 64 + np * 16 + b_row;
                ldsm4(b0[np * 2][0], b0[np * 2][1], b0[np * 2 + 1][0], b0[np * 2 + 1][1],
                      sb + (uint32_t)(2 * PLH + row * STR + k0 + b_kh) * 2);
            }
            #pragma unroll
            for (int mt = 0; mt < 2; mt++)
                #pragma unroll
                for (int nt = 0; nt < 8; nt++)
                    mma16816(acc[mt][nt], a[mt][0], a[mt][1], a[mt][2], a[mt][3],
                             b0[nt][0], b0[nt][1]);
        }
    }

    const float ISD = 0.08838834764831845f;
    int g = lane >> 2, t = lane & 3;
    #pragma unroll
    for (int mt = 0; mt < 2; mt++) {
        int mrow = m0 + wm * 32 + mt * 16 + g;
        #pragma unroll
        for (int nt = 0; nt < 8; nt++) {
            int nc = n0 + wn * 64 + nt * 8 + t * 2;
            float* c = acc[mt][nt];
            if (mode == 0) {
                float sa0 = g_invnorm[mrow], sa1 = g_invnorm[mrow + 8];
                float sb0 = g_invnorm[nc], sb1 = g_invnorm[nc + 1];
                float2 w0 = { c[0] * sa0 * sb0, c[1] * sa0 * sb1 };
                float2 w1 = { c[2] * sa1 * sb0, c[3] * sa1 * sb1 };
                *(float2*)(g_SIM + (size_t)mrow * NN + nc) = w0;
                *(float2*)(g_SIM + (size_t)(mrow + 8) * NN + nc) = w1;
            } else {
                *(__nv_bfloat162*)(g_Pb + (size_t)mrow * NN + nc) =
                    __halves2bfloat162(__float2bfloat16(c[0] * ISD),
                                       __float2bfloat16(c[1] * ISD));
                *(__nv_bfloat162*)(g_Pb + (size_t)(mrow + 8) * NN + nc) =
                    __halves2bfloat162(__float2bfloat16(c[2] * ISD),
                                       __float2bfloat16(c[3] * ISD));
            }
        }
    }
}

// ---------- classify + masked softmax + chunk occupancy flags ----------
__device__ __forceinline__ float blk_sum(float v, float* buf) {
    int t = threadIdx.x;
    buf[t] = v; __syncthreads();
    #pragma unroll
    for (int s = 128; s > 0; s >>= 1) { if (t < s) buf[t] += buf[t + s]; __syncthreads(); }
    float r = buf[0]; __syncthreads();
    return r;
}
__device__ __forceinline__ float blk_max(float v, float* buf) {
    int t = threadIdx.x;
    buf[t] = v; __syncthreads();
    #pragma unroll
    for (int s = 128; s > 0; s >>= 1) { if (t < s) buf[t] = fmaxf(buf[t], buf[t + s]); __syncthreads(); }
    float r = buf[0]; __syncthreads();
    return r;
}

__global__ __launch_bounds__(256) void classify_kernel() {
    __shared__ float s2s[NN];
    __shared__ unsigned char cds[NN];
    __shared__ float erow[DD];
    __shared__ float rbuf[256];
    __shared__ unsigned char fl[3][128];
    int i = blockIdx.x, tid = threadIdx.x;
    size_t base = (size_t)i * NN;
    if (tid < DD) erow[tid] = g_E[(size_t)i * DD + tid];
    if (tid < 128) { fl[0][tid] = 0; fl[1][tid] = 0; fl[2][tid] = 0; }
    __syncthreads();
    float inv_i = g_invnorm[i];

    float cp = 0.f, cn = 0.f, ca = 0.f, mx = -INFINITY;
    for (int j = tid; j < NN; j += 256) {
        unsigned int w = g_adjbits[i * 256 + (j >> 5)];
        int a = (w >> (j & 31)) & 1;
        float sim = g_SIM[base + j];
        float s2 = __bfloat162float(g_Pb[base + j]);
        int c = 0;
        if (a) {
            if (fabsf(sim - ALPHAC) < SIMWIN || fabsf(sim - BETAC) < SIMWIN) {
                const float* ej = g_E + (size_t)j * DD;
                float dot = 0.f;
                #pragma unroll 4
                for (int d = 0; d < DD; d++) dot += erow[d] * ej[d];
                sim = dot * inv_i * g_invnorm[j];
            }
            ca += 1.0f;
            c = (sim >= ALPHAC) ? 1 : ((sim <= BETAC) ? 2 : 3);
            fl[c - 1][j >> 6] = 1;
        }
        cds[j] = (unsigned char)c;
        g_code[base + j] = (unsigned char)c;
        s2s[j] = s2;
        cp += (c == 1) ? 1.0f : 0.0f;
        cn += (c == 2) ? 1.0f : 0.0f;
        if (c == 3) mx = fmaxf(mx, s2);
    }
    cp = blk_sum(cp, rbuf); cn = blk_sum(cn, rbuf); ca = blk_sum(ca, rbuf);
    mx = blk_max(mx, rbuf);
    if (mx == -INFINITY) mx = 0.0f;

    float s = 0.f;
    for (int j = tid; j < NN; j += 256) {
        float e = (cds[j] == 3) ? expf(s2s[j] - mx) : 0.0f;
        s2s[j] = e; s += e;
    }
    s = blk_sum(s, rbuf);
    float inv = 1.0f / fmaxf(s, 1e-30f);
    for (int j = tid; j < NN; j += 256) {
        float p = s2s[j] * inv;
        __nv_bfloat16 h = __float2bfloat16(p);
        g_Phi[base + j] = h;
        g_Plo[base + j] = __float2bfloat16(p - __bfloat162float(h));
    }
    int ib = i >> 7;
    if (tid < 128) {
        if (fl[0][tid]) g_flags[0 * 8192 + ib * 128 + tid] = 1;
        if (fl[1][tid]) g_flags[1 * 8192 + ib * 128 + tid] = 1;
        if (fl[2][tid]) g_flags[2 * 8192 + ib * 128 + tid] = 1;
    }
    if (tid == 0) {
        g_invp[i] = 1.0f / fmaxf(cp, 1.0f);
        g_invn[i] = LAMC / fmaxf(cn, 1.0f);
        g_any[i] = (ca > 0.0f) ? 1.0f : 0.0f;
    }
}

// ---------- region GEMMs: chunk skipping + code->mask expansion + merged passes ----------
__global__ __launch_bounds__(256) void region_mma() {
    extern __shared__ char smem[];
    __shared__ int lst[128];
    __shared__ int nch;
    __shared__ unsigned char fl[128];
    const int STR = 72;
    const int PLB = 128 * STR * 2;
    const int STAGE = 4 * PLB;
    const int CODE0 = 2 * STAGE;
    int tid = threadIdx.x;
    int type = blockIdx.x % 3;
    int ib = blockIdx.x / 3;
    int i0 = ib * 128;
    uint32_t sb = smem_u32(smem);

    if (tid < 128) fl[tid] = (unsigned char)g_flags[type * 8192 + ib * 128 + tid];
    __syncthreads();
    if (tid == 0) {
        int n = 0;
        for (int c = 0; c < 128; c++) if (fl[c]) lst[n++] = c;
        nch = n;
    }
    __syncthreads();
    int NCH = nch;

    const __nv_bfloat16* B0 = (type == 2) ? g_Vthi : g_Ethi;
    const __nv_bfloat16* B1 = (type == 2) ? g_Vtlo : g_Etlo;
    unsigned char target = (type == 0) ? 1 : 2;

    int wid = tid >> 5, lane = tid & 31;
    int wm = wid & 3, wn = wid >> 2;
    float acc[2][8][4];
    #pragma unroll
    for (int i = 0; i < 2; i++)
        #pragma unroll
        for (int j = 0; j < 8; j++)
            #pragma unroll
            for (int q = 0; q < 4; q++) acc[i][j][q] = 0.0f;

    int a_row = (lane & 15), a_kh = (lane >> 4) * 8;
    int b_row = (lane >> 4) * 8 + (lane & 7), b_kh = ((lane >> 3) & 1) * 8;

    auto load_chunk = [&](int s, int chunkIdx) {
        int j0 = chunkIdx * 64;
        uint32_t st = sb + (uint32_t)(s * STAGE);
        if (type == 2) {
            for (int idx = tid; idx < 1024; idx += 256) {
                int row = idx >> 3, cg = (idx & 7) * 8;
                uint32_t so = (uint32_t)(row * STR + cg) * 2;
                cpa16(st + 0 * PLB + so, g_Phi + (size_t)(i0 + row) * NN + j0 + cg);
                cpa16(st + 1 * PLB + so, g_Plo + (size_t)(i0 + row) * NN + j0 + cg);
                cpa16(st + 2 * PLB + so, B0 + (size_t)row * NN + j0 + cg);
                cpa16(st + 3 * PLB + so, B1 + (size_t)row * NN + j0 + cg);
            }
        } else {
            uint32_t cst = sb + (uint32_t)(CODE0 + s * 8192);
            for (int idx = tid; idx < 512; idx += 256) {
                int row = idx >> 2, cg = (idx & 3) * 16;
                cpa16(cst + (uint32_t)(row * 64 + cg),
                      g_code + (size_t)(i0 + row) * NN + j0 + cg);
            }
            for (int idx = tid; idx < 1024; idx += 256) {
                int row = idx >> 3, cg = (idx & 7) * 8;
                uint32_t so = (uint32_t)(row * STR + cg) * 2;
                cpa16(st + 2 * PLB + so, B0 + (size_t)row * NN + j0 + cg);
                if (type == 0)
                    cpa16(st + 3 * PLB + so, B1 + (size_t)row * NN + j0 + cg);
            }
        }
    };

    if (NCH > 0) {
        load_chunk(0, lst[0]);
        CP_COMMIT();
        for (int ci = 0; ci < NCH; ci++) {
            int s = ci & 1;
            if (ci + 1 < NCH) {
                load_chunk(s ^ 1, lst[ci + 1]);
                CP_COMMIT();
                CP_WAIT1();
            } else {
                CP_WAIT0();
            }
            __syncthreads();

            uint32_t st = sb + (uint32_t)(s * STAGE);
            if (type != 2) {
                const unsigned char* cs =
                    (const unsigned char*)smem + CODE0 + s * 8192 + (tid >> 1) * 64 + (tid & 1) * 32;
                __nv_bfloat16* dst =
                    (__nv_bfloat16*)(smem + s * STAGE) + (tid >> 1) * STR + (tid & 1) * 32;
                const __nv_bfloat16 one = __float2bfloat16(1.0f);
                const __nv_bfloat16 zero = __float2bfloat16(0.0f);
                #pragma unroll
                for (int c = 0; c < 32; c += 2) {
                    *(__nv_bfloat162*)(dst + c) = __halves2bfloat162(
                        (cs[c] == target) ? one : zero,
                        (cs[c + 1] == target) ? one : zero);
                }
                __syncthreads();
            }

            bool dualB = (type != 1);
            #pragma unroll
            for (int ks = 0; ks < 4; ks++) {
                int k0 = ks * 16;
                uint32_t a[2][4];
                #pragma unroll
                for (int mt = 0; mt < 2; mt++) {
                    int row = wm * 32 + mt * 16 + a_row;
                    ldsm4(a[mt][0], a[mt][1], a[mt][2], a[mt][3],
                          st + (uint32_t)(0 * PLB) + (uint32_t)(row * STR + k0 + a_kh) * 2);
                }
                uint32_t b0[8][2], b1[8][2];
                #pragma unroll
                for (int np = 0; np < 4; np++) {
                    int row = wn * 64 + np * 16 + b_row;
                    ldsm4(b0[np * 2][0], b0[np * 2][1], b0[np * 2 + 1][0], b0[np * 2 + 1][1],
                          st + (uint32_t)(2 * PLB) + (uint32_t)(row * STR + k0 + b_kh) * 2);
                    if (dualB)
                        ldsm4(b1[np * 2][0], b1[np * 2][1], b1[np * 2 + 1][0], b1[np * 2 + 1][1],
                              st + (uint32_t)(3 * PLB) + (uint32_t)(row * STR + k0 + b_kh) * 2);
                }
                #pragma unroll
                for (int mt = 0; mt < 2; mt++)
                    #pragma unroll
                    for (int nt = 0; nt < 8; nt++) {
                        mma16816(acc[mt][nt], a[mt][0], a[mt][1], a[mt][2], a[mt][3],
                                 b0[nt][0], b0[nt][1]);
                        if (dualB)
                            mma16816(acc[mt][nt], a[mt][0], a[mt][1], a[mt][2], a[mt][3],
                                     b1[nt][0], b1[nt][1]);
                    }
            }
            if (type == 2) {
                #pragma unroll
                for (int ks = 0; ks < 4; ks++) {
                    int k0 = ks * 16;
                    uint32_t a[2][4];
                    #pragma unroll
                    for (int mt = 0; mt < 2; mt++) {
                        int row = wm * 32 + mt * 16 + a_row;
                        ldsm4(a[mt][0], a[mt][1], a[mt][2], a[mt][3],
                              st + (uint32_t)(1 * PLB) + (uint32_t)(row * STR + k0 + a_kh) * 2);
                    }
                    uint32_t b0[8][2];
                    #pragma unroll
                    for (int np = 0; np < 4; np++) {
                        int row = wn * 64 + np * 16 + b_row;
                        ldsm4(b0[np * 2][0], b0[np * 2][1], b0[np * 2 + 1][0], b0[np * 2 + 1][1],
                              st + (uint32_t)(2 * PLB) + (uint32_t)(row * STR + k0 + b_kh) * 2);
                    }
                    #pragma unroll
                    for (int mt = 0; mt < 2; mt++)
                        #pragma unroll
                        for (int nt = 0; nt < 8; nt++)
                            mma16816(acc[mt][nt], a[mt][0], a[mt][1], a[mt][2], a[mt][3],
                                     b0[nt][0], b0[nt][1]);
                }
            }
            __syncthreads();
        }
    }

    float* dst = (type == 0) ? g_pos : (type == 1) ? g_neg : g_bnd;
    int g = lane >> 2, t = lane & 3;
    #pragma unroll
    for (int mt = 0; mt < 2; mt++) {
        int i = i0 + wm * 32 + mt * 16 + g;
        float s0 = (type == 0) ? g_invp[i] : (type == 1) ? g_invn[i] : 1.0f;
        float s1 = (type == 0) ? g_invp[i + 8] : (type == 1) ? g_invn[i + 8] : 1.0f;
        #pragma unroll
        for (int nt = 0; nt < 8; nt++) {
            int d = wn * 64 + nt * 8 + t * 2;
            float* c = acc[mt][nt];
            float2 w0 = { c[0] * s0, c[1] * s0 };
            float2 w1 = { c[2] * s1, c[3] * s1 };
            *(float2*)(dst + (size_t)i * DD + d) = w0;
            *(float2*)(dst + (size_t)(i + 8) * DD + d) = w1;
        }
    }
}

// ---------- gating MLP + fusion ----------
__global__ __launch_bounds__(256) void gate_kernel(
    const float* __restrict__ g1w, const float* __restrict__ g1b,
    const float* __restrict__ g2w, const float* __restrict__ g2b)
{
    __shared__ float x[8][512];
    __shared__ float h[8][257];
    __shared__ float gates[8][4];
    int i0 = blockIdx.x * 8, t = threadIdx.x;

    for (int q = t; q < 8 * 128; q += 256) {
        int r = q >> 7, d = q & 127;
        size_t o = (size_t)(i0 + r) * DD + d;
        x[r][d]       = g_E[o];
        x[r][128 + d] = g_pos[o];
        x[r][256 + d] = g_bnd[o];
        x[r][384 + d] = g_neg[o];
    }
    __syncthreads();

    float acc[8];
    float bb = g1b[t];
    #pragma unroll
    for (int r = 0; r < 8; r++) acc[r] = bb;
    #pragma unroll 4
    for (int kk = 0; kk < 512; kk++) {
        float w = g1w[kk * 256 + t];
        #pragma unroll
        for (int r = 0; r < 8; r++) acc[r] += x[r][kk] * w;
    }
    #pragma unroll
    for (int r = 0; r < 8; r++) h[r][t] = fmaxf(acc[r], 0.0f);
    __syncthreads();

    int wid = t >> 5, lane = t & 31;
    {
        int r = wid;
        float l0 = 0, l1 = 0, l2 = 0, l3 = 0;
        for (int kk = lane; kk < 256; kk += 32) {
            float hv = h[r][kk];
            l0 += hv * g2w[kk * 4 + 0];
            l1 += hv * g2w[kk * 4 + 1];
            l2 += hv * g2w[kk * 4 + 2];
            l3 += hv * g2w[kk * 4 + 3];
        }
        #pragma unroll
        for (int o = 16; o > 0; o >>= 1) {
            l0 += __shfl_xor_sync(0xFFFFFFFFu, l0, o);
            l1 += __shfl_xor_sync(0xFFFFFFFFu, l1, o);
            l2 += __shfl_xor_sync(0xFFFFFFFFu, l2, o);
            l3 += __shfl_xor_sync(0xFFFFFFFFu, l3, o);
        }
        if (lane == 0) {
            l0 += g2b[0]; l1 += g2b[1]; l2 += g2b[2]; l3 += g2b[3];
            float m = fmaxf(fmaxf(l0, l1), fmaxf(l2, l3));
            float e0 = expf(l0 - m), e1 = expf(l1 - m), e2 = expf(l2 - m), e3 = expf(l3 - m);
            float inv = 1.0f / (e0 + e1 + e2 + e3);
            gates[r][0] = e0 * inv; gates[r][1] = e1 * inv;
            gates[r][2] = e2 * inv; gates[r][3] = e3 * inv;
        }
    }
    __syncthreads();

    for (int q = t; q < 8 * 128; q += 256) {
        int r = q >> 7, d = q & 127;
        float any = g_any[i0 + r];
        float f;
        if (any != 0.0f)
            f = gates[r][0] * x[r][d] + gates[r][1] * x[r][128 + d]
              + gates[r][2] * x[r][256 + d] + gates[r][3] * x[r][384 + d];
        else
            f = x[r][d];
        g_agg[(size_t)(i0 + r) * DD + d] = f;
    }
}

// ---------- graph-conv layer + output ----------
__global__ __launch_bounds__(128) void gc_kernel(
    const float* __restrict__ gcw, const float* __restrict__ gcb,
    const float* __restrict__ lwp, int l, float* __restrict__ out)
{
    __shared__ float a[8][DD];
    int i0 = blockIdx.x * 8, t = threadIdx.x;
    #pragma unroll
    for (int r = 0; r < 8; r++) a[r][t] = g_agg[(size_t)(i0 + r) * DD + t];
    __syncthreads();

    float acc[8];
    float b = gcb[t];
    #pragma unroll
    for (int r = 0; r < 8; r++) acc[r] = b;
    #pragma unroll 4
    for (int kk = 0; kk < DD; kk++) {
        float w = gcw[kk * DD + t];
        #pragma unroll
        for (int r = 0; r < 8; r++) acc[r] += a[r][kk] * w;
    }

    float w0 = lwp[0], w1 = lwp[1];
    float m = fmaxf(w0, w1);
    float e0 = expf(w0 - m), e1 = expf(w1 - m);
    float lw = ((l == 0) ? e0 : e1) / (e0 + e1);

    #pragma unroll
    for (int r = 0; r < 8; r++) {
        float v = fmaxf(acc[r], 0.0f);
        size_t o = (size_t)(i0 + r) * DD + t;
        g_E[o] = v;
        if (l == 0) out[o] = lw * v;
        else        out[o] += lw * v;
    }
}

extern "C" void kernel_launch(void* const* d_in, const int* in_sizes, int n_in,
                              void* d_out, int out_size)
{
    const float* adj  = (const float*)d_in[0];
    const float* emb  = (const float*)d_in[1];
    const float* gc_w = (const float*)d_in[2];
    const float* gc_b = (const float*)d_in[3];
    const float* wq   = (const float*)d_in[4];
    const float* bq   = (const float*)d_in[5];
    const float* wk   = (const float*)d_in[6];
    const float* bk   = (const float*)d_in[7];
    const float* wv   = (const float*)d_in[8];
    const float* bv   = (const float*)d_in[9];
    const float* g1w  = (const float*)d_in[10];
    const float* g1b  = (const float*)d_in[11];
    const float* g2w  = (const float*)d_in[12];
    const float* g2b  = (const float*)d_in[13];
    const float* lw   = (const float*)d_in[14];
    float* out = (float*)d_out;

    const int simqk_smem  = 4 * 128 * 136 * 2;                 // 139264
    const int region_smem = 2 * 4 * 128 * 72 * 2 + 2 * 8192;   // 163840
    cudaFuncSetAttribute(simqk_mma, cudaFuncAttributeMaxDynamicSharedMemorySize, simqk_smem);
    cudaFuncSetAttribute(region_mma, cudaFuncAttributeMaxDynamicSharedMemorySize, region_smem);

    init_kernel<<<(NN * DD) / 256, 256>>>(emb);
    adjbits_kernel<<<(NN * NN / 32) / 256, 256>>>(adj);

    for (int l = 0; l < 2; l++) {
        norm_kernel<<<NN * 32 / 256, 256>>>();
        qkv_kernel<<<NN / 8, 128>>>(wq, bq, wk, bk, wv, bv);
        transpose_split_kernel<<<dim3(NN / 32, DD / 32), 256>>>();
        simqk_mma<<<dim3(64, 64), 256, simqk_smem>>>(0);
        simqk_mma<<<dim3(64, 64), 256, simqk_smem>>>(1);
        zero_flags_kernel<<<(3 * 64 * 128) / 256, 256>>>();
        classify_kernel<<<NN, 256>>>();
        region_mma<<<3 * (NN / 128), 256, region_smem>>>();
        gate_kernel<<<NN / 8, 256>>>(g1w, g1b, g2w, g2b);
        gc_kernel<<<NN / 8, 128>>>(gc_w + (size_t)l * DD * DD, gc_b + (size_t)l * DD,
                                   lw, l, out);
    }
}

// round 14
// speedup vs baseline: 1.2047x; 1.2047x over previous
#include <cuda_runtime.h>
#include <cuda_bf16.h>
#include <math.h>
#include <stdint.h>

#define NN 8192
#define DD 128
#define ALPHAC 0.7f
#define BETAC  0.3f
#define LAMC   0.1f
#define SIMWIN 1e-4f

static __device__ float g_E[NN * DD];
static __device__ float g_V[NN * DD];
static __device__ float g_invnorm[NN];
static __device__ float g_invp[NN];
static __device__ float g_invn[NN];
static __device__ float g_any[NN];
static __device__ float g_SIM[(size_t)NN * NN];                // sim (fp32)
static __device__ float g_P[(size_t)NN * NN];                  // attn scores (fp32)
static __device__ unsigned char g_code[(size_t)NN * NN];       // region code 0..3
static __device__ __nv_bfloat16 g_Phi[(size_t)NN * NN];
static __device__ __nv_bfloat16 g_Plo[(size_t)NN * NN];
static __device__ unsigned int g_adjbits[NN * NN / 32];
static __device__ int g_flags[3 * 64 * 128];                   // [type][iblock][jchunk]
static __device__ __nv_bfloat16 g_Ehi[NN * DD], g_Elo[NN * DD];
static __device__ __nv_bfloat16 g_Qhi[NN * DD];
static __device__ __nv_bfloat16 g_Khi[NN * DD], g_Klo[NN * DD];
static __device__ __nv_bfloat16 g_Ethi[DD * NN], g_Etlo[DD * NN];
static __device__ __nv_bfloat16 g_Vthi[DD * NN], g_Vtlo[DD * NN];
static __device__ float g_pos[NN * DD];
static __device__ float g_neg[NN * DD];
static __device__ float g_bnd[NN * DD];
static __device__ float g_agg[NN * DD];

// ---------- baseline-PTX helpers ----------
__device__ __forceinline__ uint32_t smem_u32(const void* p) {
    uint32_t a;
    asm("{ .reg .u64 t; cvta.to.shared.u64 t, %1; cvt.u32.u64 %0, t; }" : "=r"(a) : "l"(p));
    return a;
}
__device__ __forceinline__ void ldsm4(uint32_t& r0, uint32_t& r1, uint32_t& r2, uint32_t& r3,
                                      uint32_t addr) {
    asm volatile("ldmatrix.sync.aligned.m8n8.x4.shared.b16 {%0,%1,%2,%3}, [%4];"
                 : "=r"(r0), "=r"(r1), "=r"(r2), "=r"(r3) : "r"(addr));
}
__device__ __forceinline__ void mma16816(float* c, uint32_t a0, uint32_t a1, uint32_t a2,
                                         uint32_t a3, uint32_t b0, uint32_t b1) {
    asm volatile(
        "mma.sync.aligned.m16n8k16.row.col.f32.bf16.bf16.f32 "
        "{%0,%1,%2,%3},{%4,%5,%6,%7},{%8,%9},{%0,%1,%2,%3};"
        : "+f"(c[0]), "+f"(c[1]), "+f"(c[2]), "+f"(c[3])
        : "r"(a0), "r"(a1), "r"(a2), "r"(a3), "r"(b0), "r"(b1));
}
__device__ __forceinline__ void cpa16(uint32_t saddr, const void* g) {
    asm volatile("cp.async.ca.shared.global [%0], [%1], 16;" :: "r"(saddr), "l"(g));
}
#define CP_COMMIT() asm volatile("cp.async.commit_group;" ::: "memory")
#define CP_WAIT0()  asm volatile("cp.async.wait_group 0;" ::: "memory")
#define CP_WAIT1()  asm volatile("cp.async.wait_group 1;" ::: "memory")

// ---------- small prep ----------
__global__ void init_kernel(const float* __restrict__ emb) {
    int idx = blockIdx.x * 256 + threadIdx.x;
    g_E[idx] = emb[idx];
}
__global__ void adjbits_kernel(const float* __restrict__ adj) {
    int w = blockIdx.x * 256 + threadIdx.x;
    size_t base = (size_t)w * 32;
    unsigned int bits = 0;
    #pragma unroll 8
    for (int b = 0; b < 32; b++) bits |= (adj[base + b] != 0.0f) ? (1u << b) : 0u;
    g_adjbits[w] = bits;
}
// g_any is adjacency-only: compute once (one warp per row)
__global__ void any_kernel() {
    int i = (blockIdx.x * blockDim.x + threadIdx.x) >> 5;
    if (i >= NN) return;
    int lane = threadIdx.x & 31;
    unsigned int v = 0;
    #pragma unroll
    for (int w = 0; w < 8; w++) v |= g_adjbits[i * 256 + lane + w * 32];
    v = __any_sync(0xFFFFFFFFu, v != 0);
    if (lane == 0) g_any[i] = v ? 1.0f : 0.0f;
}
__global__ void zero_flags_kernel() {
    g_flags[blockIdx.x * 256 + threadIdx.x] = 0;
}
// norm + E hi/lo split (one warp per row)
__global__ void norm_kernel() {
    int gw = (blockIdx.x * blockDim.x + threadIdx.x) >> 5;
    if (gw >= NN) return;
    int lane = threadIdx.x & 31;
    size_t o = (size_t)gw * DD + lane * 4;
    float4 v = *(const float4*)(g_E + o);
    float s = v.x * v.x + v.y * v.y + v.z * v.z + v.w * v.w;
    #pragma unroll
    for (int of = 16; of > 0; of >>= 1) s += __shfl_xor_sync(0xFFFFFFFFu, s, of);
    if (lane == 0) g_invnorm[gw] = 1.0f / fmaxf(sqrtf(s), 1e-8f);
    __nv_bfloat16 hx = __float2bfloat16(v.x), hy = __float2bfloat16(v.y);
    __nv_bfloat16 hz = __float2bfloat16(v.z), hw = __float2bfloat16(v.w);
    *(__nv_bfloat162*)(g_Ehi + o)     = __halves2bfloat162(hx, hy);
    *(__nv_bfloat162*)(g_Ehi + o + 2) = __halves2bfloat162(hz, hw);
    *(__nv_bfloat162*)(g_Elo + o) = __halves2bfloat162(
        __float2bfloat16(v.x - __bfloat162float(hx)), __float2bfloat16(v.y - __bfloat162float(hy)));
    *(__nv_bfloat162*)(g_Elo + o + 2) = __halves2bfloat162(
        __float2bfloat16(v.z - __bfloat162float(hz)), __float2bfloat16(v.w - __bfloat162float(hw)));
}

// QKV + direct bf16 split writes
__global__ __launch_bounds__(128) void qkv_kernel(
    const float* __restrict__ wq, const float* __restrict__ bq,
    const float* __restrict__ wk, const float* __restrict__ bk,
    const float* __restrict__ wv, const float* __restrict__ bv)
{
    __shared__ float e[8][DD];
    int i0 = blockIdx.x * 8, t = threadIdx.x;
    #pragma unroll
    for (int r = 0; r < 8; r++) e[r][t] = g_E[(size_t)(i0 + r) * DD + t];
    __syncthreads();
    float q[8], k[8], v[8];
    float bqv = bq[t], bkv = bk[t], bvv = bv[t];
    #pragma unroll
    for (int r = 0; r < 8; r++) { q[r] = bqv; k[r] = bkv; v[r] = bvv; }
    #pragma unroll 4
    for (int kk = 0; kk < DD; kk++) {
        float a = wq[kk * DD + t], b = wk[kk * DD + t], c = wv[kk * DD + t];
        #pragma unroll
        for (int r = 0; r < 8; r++) {
            float x = e[r][kk];
            q[r] += x * a; k[r] += x * b; v[r] += x * c;
        }
    }
    #pragma unroll
    for (int r = 0; r < 8; r++) {
        size_t o = (size_t)(i0 + r) * DD + t;
        g_Qhi[o] = __float2bfloat16(q[r]);
        __nv_bfloat16 kh = __float2bfloat16(k[r]);
        g_Khi[o] = kh;
        g_Klo[o] = __float2bfloat16(k[r] - __bfloat162float(kh));
        g_V[o] = v[r];
    }
}

__global__ __launch_bounds__(256) void transpose_split_kernel() {
    __shared__ float te[32][33], tv[32][33];
    int jb = blockIdx.x * 32, db = blockIdx.y * 32;
    int tx = threadIdx.x & 31, ty = threadIdx.x >> 5;
    #pragma unroll
    for (int r = 0; r < 32; r += 8) {
        te[ty + r][tx] = g_E[(size_t)(jb + ty + r) * DD + db + tx];
        tv[ty + r][tx] = g_V[(size_t)(jb + ty + r) * DD + db + tx];
    }
    __syncthreads();
    #pragma unroll
    for (int r = 0; r < 32; r += 8) {
        size_t o = (size_t)(db + ty + r) * NN + jb + tx;
        float e = te[tx][ty + r];
        __nv_bfloat16 h = __float2bfloat16(e);
        g_Ethi[o] = h; g_Etlo[o] = __float2bfloat16(e - __bfloat162float(h));
        float v = tv[tx][ty + r];
        h = __float2bfloat16(v);
        g_Vthi[o] = h; g_Vtlo[o] = __float2bfloat16(v - __bfloat162float(h));
    }
}

// ---------- NT GEMM via mma.sync, merged split-passes ----------
// mode0: SIM = (E E^T)*invn_i*invn_j — A0·(B0,B1) merged + A1·B0
// mode1: P = (Q K^T)/sqrt(D) — A0·(B0,B1) merged (2-pass)
__global__ __launch_bounds__(256) void simqk_mma(int mode) {
    extern __shared__ char smem[];
    const int STR = 136;
    const int PLH = 128 * STR;
    __nv_bfloat16* sm = (__nv_bfloat16*)smem;
    const __nv_bfloat16* gA0 = (mode == 0) ? g_Ehi : g_Qhi;
    const __nv_bfloat16* gB0 = (mode == 0) ? g_Ehi : g_Khi;
    const __nv_bfloat16* gB1 = (mode == 0) ? g_Elo : g_Klo;
    float* C = (mode == 0) ? g_SIM : g_P;
    int tid = threadIdx.x;
    int m0 = blockIdx.y * 128, n0 = blockIdx.x * 128;

    for (int idx = tid; idx < 128 * 16; idx += 256) {
        int row = idx >> 4, cg = (idx & 15) * 8;
        size_t gm = (size_t)(m0 + row) * DD + cg;
        size_t gn = (size_t)(n0 + row) * DD + cg;
        int so = row * STR + cg;
        *(uint4*)(sm + 0 * PLH + so) = *(const uint4*)(gA0 + gm);
        if (mode == 0)
            *(uint4*)(sm + 1 * PLH + so) = *(const uint4*)(g_Elo + gm);
        *(uint4*)(sm + 2 * PLH + so) = *(const uint4*)(gB0 + gn);
        *(uint4*)(sm + 3 * PLH + so) = *(const uint4*)(gB1 + gn);
    }
    __syncthreads();

    int wid = tid >> 5, lane = tid & 31;
    int wm = wid & 3, wn = wid >> 2;
    uint32_t sb = smem_u32(smem);
    float acc[2][8][4];
    #pragma unroll
    for (int i = 0; i < 2; i++)
        #pragma unroll
        for (int j = 0; j < 8; j++)
            #pragma unroll
            for (int q = 0; q < 4; q++) acc[i][j][q] = 0.0f;

    int a_row = (lane & 15), a_kh = (lane >> 4) * 8;
    int b_row = (lane >> 4) * 8 + (lane & 7), b_kh = ((lane >> 3) & 1) * 8;

    #pragma unroll
    for (int ks = 0; ks < 8; ks++) {
        int k0 = ks * 16;
        uint32_t a[2][4];
        #pragma unroll
        for (int mt = 0; mt < 2; mt++) {
            int row = wm * 32 + mt * 16 + a_row;
            ldsm4(a[mt][0], a[mt][1], a[mt][2], a[mt][3],
                  sb + (uint32_t)(0 * PLH + row * STR + k0 + a_kh) * 2);
        }
        uint32_t b0[8][2], b1[8][2];
        #pragma unroll
        for (int np = 0; np < 4; np++) {
            int row = wn * 64 + np * 16 + b_row;
            ldsm4(b0[np * 2][0], b0[np * 2][1], b0[np * 2 + 1][0], b0[np * 2 + 1][1],
                  sb + (uint32_t)(2 * PLH + row * STR + k0 + b_kh) * 2);
            ldsm4(b1[np * 2][0], b1[np * 2][1], b1[np * 2 + 1][0], b1[np * 2 + 1][1],
                  sb + (uint32_t)(3 * PLH + row * STR + k0 + b_kh) * 2);
        }
        #pragma unroll
        for (int mt = 0; mt < 2; mt++)
            #pragma unroll
            for (int nt = 0; nt < 8; nt++) {
                mma16816(acc[mt][nt], a[mt][0], a[mt][1], a[mt][2], a[mt][3],
                         b0[nt][0], b0[nt][1]);
                mma16816(acc[mt][nt], a[mt][0], a[mt][1], a[mt][2], a[mt][3],
                         b1[nt][0], b1[nt][1]);
            }
    }
    if (mode == 0) {
        #pragma unroll
        for (int ks = 0; ks < 8; ks++) {
            int k0 = ks * 16;
            uint32_t a[2][4];
            #pragma unroll
            for (int mt = 0; mt < 2; mt++) {
                int row = wm * 32 + mt * 16 + a_row;
                ldsm4(a[mt][0], a[mt][1], a[mt][2], a[mt][3],
                      sb + (uint32_t)(1 * PLH + row * STR + k0 + a_kh) * 2);
            }
            uint32_t b0[8][2];
            #pragma unroll
            for (int np = 0; np < 4; np++) {
                int row = wn * 64 + np * 16 + b_row;
                ldsm4(b0[np * 2][0], b0[np * 2][1], b0[np * 2 + 1][0], b0[np * 2 + 1][1],
                      sb + (uint32_t)(2 * PLH + row * STR + k0 + b_kh) * 2);
            }
            #pragma unroll
            for (int mt = 0; mt < 2; mt++)
                #pragma unroll
                for (int nt = 0; nt < 8; nt++)
                    mma16816(acc[mt][nt], a[mt][0], a[mt][1], a[mt][2], a[mt][3],
                             b0[nt][0], b0[nt][1]);
        }
    }

    const float ISD = 0.08838834764831845f;
    int g = lane >> 2, t = lane & 3;
    #pragma unroll
    for (int mt = 0; mt < 2; mt++) {
        int mrow = m0 + wm * 32 + mt * 16 + g;
        float sa0 = (mode == 0) ? g_invnorm[mrow] : ISD;
        float sa1 = (mode == 0) ? g_invnorm[mrow + 8] : ISD;
        #pragma unroll
        for (int nt = 0; nt < 8; nt++) {
            int nc = n0 + wn * 64 + nt * 8 + t * 2;
            float sb0 = (mode == 0) ? g_invnorm[nc] : 1.0f;
            float sb1 = (mode == 0) ? g_invnorm[nc + 1] : 1.0f;
            float* c = acc[mt][nt];
            float2 w0 = { c[0] * sa0 * sb0, c[1] * sa0 * sb1 };
            float2 w1 = { c[2] * sa1 * sb0, c[3] * sa1 * sb1 };
            *(float2*)(C + (size_t)mrow * NN + nc) = w0;
            *(float2*)(C + (size_t)(mrow + 8) * NN + nc) = w1;
        }
    }
}

// ---------- classify + masked softmax + chunk occupancy flags (vectorized) ----------
__device__ __forceinline__ float blk_sum(float v, float* buf) {
    int t = threadIdx.x;
    buf[t] = v; __syncthreads();
    #pragma unroll
    for (int s = 128; s > 0; s >>= 1) { if (t < s) buf[t] += buf[t + s]; __syncthreads(); }
    float r = buf[0]; __syncthreads();
    return r;
}
__device__ __forceinline__ float blk_max(float v, float* buf) {
    int t = threadIdx.x;
    buf[t] = v; __syncthreads();
    #pragma unroll
    for (int s = 128; s > 0; s >>= 1) { if (t < s) buf[t] = fmaxf(buf[t], buf[t + s]); __syncthreads(); }
    float r = buf[0]; __syncthreads();
    return r;
}

__global__ __launch_bounds__(256) void classify_kernel() {
    __shared__ float s2s[NN];
    __shared__ unsigned char cds[NN];
    __shared__ float erow[DD];
    __shared__ float rbuf[256];
    __shared__ unsigned char fl[3][128];
    int i = blockIdx.x, tid = threadIdx.x;
    size_t base = (size_t)i * NN;
    if (tid < DD) erow[tid] = g_E[(size_t)i * DD + tid];
    if (tid < 128) { fl[0][tid] = 0; fl[1][tid] = 0; fl[2][tid] = 0; }
    __syncthreads();
    float inv_i = g_invnorm[i];

    float cp = 0.f, cn = 0.f, mx = -INFINITY;
    for (int j = tid * 4; j < NN; j += 1024) {
        unsigned int w = g_adjbits[i * 256 + (j >> 5)];
        float4 sim4 = *(const float4*)(g_SIM + base + j);
        float4 s4 = *(const float4*)(g_P + base + j);
        float sims[4] = { sim4.x, sim4.y, sim4.z, sim4.w };
        float ss[4] = { s4.x, s4.y, s4.z, s4.w };
        int chunk = j >> 6;
        uchar4 k4;
        unsigned char* kp = (unsigned char*)&k4;
        #pragma unroll
        for (int e = 0; e < 4; e++) {
            int a = (w >> ((j + e) & 31)) & 1;
            int c = 0;
            if (a) {
                float sim = sims[e];
                if (fabsf(sim - ALPHAC) < SIMWIN || fabsf(sim - BETAC) < SIMWIN) {
                    const float* ej = g_E + (size_t)(j + e) * DD;
                    float dot = 0.f;
                    #pragma unroll 4
                    for (int d = 0; d < DD; d++) dot += erow[d] * ej[d];
                    sim = dot * inv_i * g_invnorm[j + e];
                }
                c = (sim >= ALPHAC) ? 1 : ((sim <= BETAC) ? 2 : 3);
                fl[c - 1][chunk] = 1;
                cp += (c == 1) ? 1.0f : 0.0f;
                cn += (c == 2) ? 1.0f : 0.0f;
                if (c == 3) mx = fmaxf(mx, ss[e]);
            }
            kp[e] = (unsigned char)c;
            cds[j + e] = (unsigned char)c;
            s2s[j + e] = ss[e];
        }
        *(uchar4*)(g_code + base + j) = k4;
    }
    cp = blk_sum(cp, rbuf);
    cn = blk_sum(cn, rbuf);
    mx = blk_max(mx, rbuf);
    if (mx == -INFINITY) mx = 0.0f;

    float s = 0.f;
    for (int j = tid * 2; j < NN; j += 512) {
        float e0 = (cds[j] == 3) ? expf(s2s[j] - mx) : 0.0f;
        float e1 = (cds[j + 1] == 3) ? expf(s2s[j + 1] - mx) : 0.0f;
        s2s[j] = e0; s2s[j + 1] = e1;
        s += e0 + e1;
    }
    s = blk_sum(s, rbuf);
    float inv = 1.0f / fmaxf(s, 1e-30f);
    for (int j = tid * 2; j < NN; j += 512) {
        float p0 = s2s[j] * inv, p1 = s2s[j + 1] * inv;
        __nv_bfloat16 h0 = __float2bfloat16(p0), h1 = __float2bfloat16(p1);
        *(__nv_bfloat162*)(g_Phi + base + j) = __halves2bfloat162(h0, h1);
        *(__nv_bfloat162*)(g_Plo + base + j) = __halves2bfloat162(
            __float2bfloat16(p0 - __bfloat162float(h0)),
            __float2bfloat16(p1 - __bfloat162float(h1)));
    }
    int ib = i >> 7;
    if (tid < 128) {
        if (fl[0][tid]) g_flags[0 * 8192 + ib * 128 + tid] = 1;
        if (fl[1][tid]) g_flags[1 * 8192 + ib * 128 + tid] = 1;
        if (fl[2][tid]) g_flags[2 * 8192 + ib * 128 + tid] = 1;
    }
    if (tid == 0) {
        g_invp[i] = 1.0f / fmaxf(cp, 1.0f);
        g_invn[i] = LAMC / fmaxf(cn, 1.0f);
    }
}

// ---------- region GEMMs: chunk skipping + code->mask expansion (R11, unmerged passes) ----------
__global__ __launch_bounds__(256) void region_mma() {
    extern __shared__ char smem[];
    __shared__ int lst[128];
    __shared__ int nch;
    __shared__ unsigned char fl[128];
    const int STR = 72;
    const int PLB = 128 * STR * 2;
    const int STAGE = 4 * PLB;
    const int CODE0 = 2 * STAGE;
    int tid = threadIdx.x;
    int type = blockIdx.x % 3;
    int ib = blockIdx.x / 3;
    int i0 = ib * 128;
    uint32_t sb = smem_u32(smem);

    if (tid < 128) fl[tid] = (unsigned char)g_flags[type * 8192 + ib * 128 + tid];
    __syncthreads();
    if (tid == 0) {
        int n = 0;
        for (int c = 0; c < 128; c++) if (fl[c]) lst[n++] = c;
        nch = n;
    }
    __syncthreads();
    int NCH = nch;

    const __nv_bfloat16* B0 = (type == 2) ? g_Vthi : g_Ethi;
    const __nv_bfloat16* B1 = (type == 2) ? g_Vtlo : g_Etlo;
    int npass = (type == 0) ? 2 : (type == 1) ? 1 : 3;
    unsigned char target = (type == 0) ? 1 : 2;

    int wid = tid >> 5, lane = tid & 31;
    int wm = wid & 3, wn = wid >> 2;
    float acc[2][8][4];
    #pragma unroll
    for (int i = 0; i < 2; i++)
        #pragma unroll
        for (int j = 0; j < 8; j++)
            #pragma unroll
            for (int q = 0; q < 4; q++) acc[i][j][q] = 0.0f;

    int a_row = (lane & 15), a_kh = (lane >> 4) * 8;
    int b_row = (lane >> 4) * 8 + (lane & 7), b_kh = ((lane >> 3) & 1) * 8;
    const int AP[3] = {0, 0, 1}, BP[3] = {2, 3, 2};

    auto load_chunk = [&](int s, int chunkIdx) {
        int j0 = chunkIdx * 64;
        uint32_t st = sb + (uint32_t)(s * STAGE);
        if (type == 2) {
            for (int idx = tid; idx < 1024; idx += 256) {
                int row = idx >> 3, cg = (idx & 7) * 8;
                uint32_t so = (uint32_t)(row * STR + cg) * 2;
                cpa16(st + 0 * PLB + so, g_Phi + (size_t)(i0 + row) * NN + j0 + cg);
                cpa16(st + 1 * PLB + so, g_Plo + (size_t)(i0 + row) * NN + j0 + cg);
                cpa16(st + 2 * PLB + so, B0 + (size_t)row * NN + j0 + cg);
                cpa16(st + 3 * PLB + so, B1 + (size_t)row * NN + j0 + cg);
            }
        } else {
            uint32_t cst = sb + (uint32_t)(CODE0 + s * 8192);
            for (int idx = tid; idx < 512; idx += 256) {
                int row = idx >> 2, cg = (idx & 3) * 16;
                cpa16(cst + (uint32_t)(row * 64 + cg),
                      g_code + (size_t)(i0 + row) * NN + j0 + cg);
            }
            for (int idx = tid; idx < 1024; idx += 256) {
                int row = idx >> 3, cg = (idx & 7) * 8;
                uint32_t so = (uint32_t)(row * STR + cg) * 2;
                cpa16(st + 2 * PLB + so, B0 + (size_t)row * NN + j0 + cg);
                if (type == 0)
                    cpa16(st + 3 * PLB + so, B1 + (size_t)row * NN + j0 + cg);
            }
        }
    };

    if (NCH > 0) {
        load_chunk(0, lst[0]);
        CP_COMMIT();
        for (int ci = 0; ci < NCH; ci++) {
            int s = ci & 1;
            if (ci + 1 < NCH) {
                load_chunk(s ^ 1, lst[ci + 1]);
                CP_COMMIT();
                CP_WAIT1();
            } else {
                CP_WAIT0();
            }
            __syncthreads();

            uint32_t st = sb + (uint32_t)(s * STAGE);
            if (type != 2) {
                const unsigned char* cs =
                    (const unsigned char*)smem + CODE0 + s * 8192 + (tid >> 1) * 64 + (tid & 1) * 32;
                __nv_bfloat16* dst =
                    (__nv_bfloat16*)(smem + s * STAGE) + (tid >> 1) * STR + (tid & 1) * 32;
                const __nv_bfloat16 one = __float2bfloat16(1.0f);
                const __nv_bfloat16 zero = __float2bfloat16(0.0f);
                #pragma unroll
                for (int c = 0; c < 32; c += 2) {
                    *(__nv_bfloat162*)(dst + c) = __halves2bfloat162(
                        (cs[c] == target) ? one : zero,
                        (cs[c + 1] == target) ? one : zero);
                }
                __syncthreads();
            }

            for (int p = 0; p < npass; p++) {
                uint32_t abase = st + (uint32_t)(AP[p] * PLB);
                uint32_t bbase = st + (uint32_t)(BP[p] * PLB);
                #pragma unroll
                for (int ks = 0; ks < 4; ks++) {
                    int k0 = ks * 16;
                    uint32_t a[2][4];
                    #pragma unroll
                    for (int mt = 0; mt < 2; mt++) {
                        int row = wm * 32 + mt * 16 + a_row;
                        ldsm4(a[mt][0], a[mt][1], a[mt][2], a[mt][3],
                              abase + (uint32_t)(row * STR + k0 + a_kh) * 2);
                    }
                    uint32_t b[8][2];
                    #pragma unroll
                    for (int np = 0; np < 4; np++) {
                        int row = wn * 64 + np * 16 + b_row;
                        ldsm4(b[np * 2][0], b[np * 2][1], b[np * 2 + 1][0], b[np * 2 + 1][1],
                              bbase + (uint32_t)(row * STR + k0 + b_kh) * 2);
                    }
                    #pragma unroll
                    for (int mt = 0; mt < 2; mt++)
                        #pragma unroll
                        for (int nt = 0; nt < 8; nt++)
                            mma16816(acc[mt][nt], a[mt][0], a[mt][1], a[mt][2], a[mt][3],
                                     b[nt][0], b[nt][1]);
                }
            }
            __syncthreads();
        }
    }

    float* dst = (type == 0) ? g_pos : (type == 1) ? g_neg : g_bnd;
    int g = lane >> 2, t = lane & 3;
    #pragma unroll
    for (int mt = 0; mt < 2; mt++) {
        int i = i0 + wm * 32 + mt * 16 + g;
        float s0 = (type == 0) ? g_invp[i] : (type == 1) ? g_invn[i] : 1.0f;
        float s1 = (type == 0) ? g_invp[i + 8] : (type == 1) ? g_invn[i + 8] : 1.0f;
        #pragma unroll
        for (int nt = 0; nt < 8; nt++) {
            int d = wn * 64 + nt * 8 + t * 2;
            float* c = acc[mt][nt];
            float2 w0 = { c[0] * s0, c[1] * s0 };
            float2 w1 = { c[2] * s1, c[3] * s1 };
            *(float2*)(dst + (size_t)i * DD + d) = w0;
            *(float2*)(dst + (size_t)(i + 8) * DD + d) = w1;
        }
    }
}

// ---------- gating MLP + fusion ----------
__global__ __launch_bounds__(256) void gate_kernel(
    const float* __restrict__ g1w, const float* __restrict__ g1b,
    const float* __restrict__ g2w, const float* __restrict__ g2b)
{
    __shared__ float x[8][512];
    __shared__ float h[8][257];
    __shared__ float gates[8][4];
    int i0 = blockIdx.x * 8, t = threadIdx.x;

    for (int q = t; q < 8 * 128; q += 256) {
        int r = q >> 7, d = q & 127;
        size_t o = (size_t)(i0 + r) * DD + d;
        x[r][d]       = g_E[o];
        x[r][128 + d] = g_pos[o];
        x[r][256 + d] = g_bnd[o];
        x[r][384 + d] = g_neg[o];
    }
    __syncthreads();

    float acc[8];
    float bb = g1b[t];
    #pragma unroll
    for (int r = 0; r < 8; r++) acc[r] = bb;
    #pragma unroll 4
    for (int kk = 0; kk < 512; kk++) {
        float w = g1w[kk * 256 + t];
        #pragma unroll
        for (int r = 0; r < 8; r++) acc[r] += x[r][kk] * w;
    }
    #pragma unroll
    for (int r = 0; r < 8; r++) h[r][t] = fmaxf(acc[r], 0.0f);
    __syncthreads();

    int wid = t >> 5, lane = t & 31;
    {
        int r = wid;
        float l0 = 0, l1 = 0, l2 = 0, l3 = 0;
        for (int kk = lane; kk < 256; kk += 32) {
            float hv = h[r][kk];
            l0 += hv * g2w[kk * 4 + 0];
            l1 += hv * g2w[kk * 4 + 1];
            l2 += hv * g2w[kk * 4 + 2];
            l3 += hv * g2w[kk * 4 + 3];
        }
        #pragma unroll
        for (int o = 16; o > 0; o >>= 1) {
            l0 += __shfl_xor_sync(0xFFFFFFFFu, l0, o);
            l1 += __shfl_xor_sync(0xFFFFFFFFu, l1, o);
            l2 += __shfl_xor_sync(0xFFFFFFFFu, l2, o);
            l3 += __shfl_xor_sync(0xFFFFFFFFu, l3, o);
        }
        if (lane == 0) {
            l0 += g2b[0]; l1 += g2b[1]; l2 += g2b[2]; l3 += g2b[3];
            float m = fmaxf(fmaxf(l0, l1), fmaxf(l2, l3));
            float e0 = expf(l0 - m), e1 = expf(l1 - m), e2 = expf(l2 - m), e3 = expf(l3 - m);
            float inv = 1.0f / (e0 + e1 + e2 + e3);
            gates[r][0] = e0 * inv; gates[r][1] = e1 * inv;
            gates[r][2] = e2 * inv; gates[r][3] = e3 * inv;
        }
    }
    __syncthreads();

    for (int q = t; q < 8 * 128; q += 256) {
        int r = q >> 7, d = q & 127;
        float any = g_any[i0 + r];
        float f;
        if (any != 0.0f)
            f = gates[r][0] * x[r][d] + gates[r][1] * x[r][128 + d]
              + gates[r][2] * x[r][256 + d] + gates[r][3] * x[r][384 + d];
        else
            f = x[r][d];
        g_agg[(size_t)(i0 + r) * DD + d] = f;
    }
}

// ---------- graph-conv layer + output ----------
__global__ __launch_bounds__(128) void gc_kernel(
    const float* __restrict__ gcw, const float* __restrict__ gcb,
    const float* __restrict__ lwp, int l, float* __restrict__ out)
{
    __shared__ float a[8][DD];
    int i0 = blockIdx.x * 8, t = threadIdx.x;
    #pragma unroll
    for (int r = 0; r < 8; r++) a[r][t] = g_agg[(size_t)(i0 + r) * DD + t];
    __syncthreads();

    float acc[8];
    float b = gcb[t];
    #pragma unroll
    for (int r = 0; r < 8; r++) acc[r] = b;
    #pragma unroll 4
    for (int kk = 0; kk < DD; kk++) {
        float w = gcw[kk * DD + t];
        #pragma unroll
        for (int r = 0; r < 8; r++) acc[r] += a[r][kk] * w;
    }

    float w0 = lwp[0], w1 = lwp[1];
    float m = fmaxf(w0, w1);
    float e0 = expf(w0 - m), e1 = expf(w1 - m);
    float lw = ((l == 0) ? e0 : e1) / (e0 + e1);

    #pragma unroll
    for (int r = 0; r < 8; r++) {
        float v = fmaxf(acc[r], 0.0f);
        size_t o = (size_t)(i0 + r) * DD + t;
        g_E[o] = v;
        if (l == 0) out[o] = lw * v;
        else        out[o] += lw * v;
    }
}

extern "C" void kernel_launch(void* const* d_in, const int* in_sizes, int n_in,
                              void* d_out, int out_size)
{
    const float* adj  = (const float*)d_in[0];
    const float* emb  = (const float*)d_in[1];
    const float* gc_w = (const float*)d_in[2];
    const float* gc_b = (const float*)d_in[3];
    const float* wq   = (const float*)d_in[4];
    const float* bq   = (const float*)d_in[5];
    const float* wk   = (const float*)d_in[6];
    const float* bk   = (const float*)d_in[7];
    const float* wv   = (const float*)d_in[8];
    const float* bv   = (const float*)d_in[9];
    const float* g1w  = (const float*)d_in[10];
    const float* g1b  = (const float*)d_in[11];
    const float* g2w  = (const float*)d_in[12];
    const float* g2b  = (const float*)d_in[13];
    const float* lw   = (const float*)d_in[14];
    float* out = (float*)d_out;

    const int simqk_smem  = 4 * 128 * 136 * 2;                 // 139264
    const int region_smem = 2 * 4 * 128 * 72 * 2 + 2 * 8192;   // 163840
    cudaFuncSetAttribute(simqk_mma, cudaFuncAttributeMaxDynamicSharedMemorySize, simqk_smem);
    cudaFuncSetAttribute(region_mma, cudaFuncAttributeMaxDynamicSharedMemorySize, region_smem);

    init_kernel<<<(NN * DD) / 256, 256>>>(emb);
    adjbits_kernel<<<(NN * NN / 32) / 256, 256>>>(adj);
    any_kernel<<<NN * 32 / 256, 256>>>();

    for (int l = 0; l < 2; l++) {
        norm_kernel<<<NN * 32 / 256, 256>>>();
        qkv_kernel<<<NN / 8, 128>>>(wq, bq, wk, bk, wv, bv);
        transpose_split_kernel<<<dim3(NN / 32, DD / 32), 256>>>();
        simqk_mma<<<dim3(64, 64), 256, simqk_smem>>>(0);
        simqk_mma<<<dim3(64, 64), 256, simqk_smem>>>(1);
        zero_flags_kernel<<<(3 * 64 * 128) / 256, 256>>>();
        classify_kernel<<<NN, 256>>>();
        region_mma<<<3 * (NN / 128), 256, region_smem>>>();
        gate_kernel<<<NN / 8, 256>>>(g1w, g1b, g2w, g2b);
        gc_kernel<<<NN / 8, 128>>>(gc_w + (size_t)l * DD * DD, gc_b + (size_t)l * DD,
                                   lw, l, out);
    }
}

// round 15
// speedup vs baseline: 1.2476x; 1.0356x over previous
#include <cuda_runtime.h>
#include <cuda_bf16.h>
#include <math.h>
#include <stdint.h>

#define NN 8192
#define DD 128
#define ALPHAC 0.7f
#define BETAC  0.3f
#define LAMC   0.1f
#define SIMWIN 1e-4f

static __device__ float g_E[NN * DD];
static __device__ float g_V[NN * DD];
static __device__ float g_invnorm[NN];
static __device__ float g_invp[NN];
static __device__ float g_invn[NN];
static __device__ float g_any[NN];
static __device__ float g_SIM[(size_t)NN * NN];                // sim (fp32)
static __device__ float g_P[(size_t)NN * NN];                  // attn scores (fp32)
static __device__ unsigned char g_code[(size_t)NN * NN];       // region code 0..3
static __device__ __nv_bfloat16 g_Phi[(size_t)NN * NN];
static __device__ __nv_bfloat16 g_Plo[(size_t)NN * NN];
static __device__ unsigned int g_adjbits[NN * NN / 32];
static __device__ int g_flags[3 * 64 * 128];                   // [type][iblock][jchunk]
static __device__ __nv_bfloat16 g_Ehi[NN * DD], g_Elo[NN * DD];
static __device__ __nv_bfloat16 g_Qhi[NN * DD];
static __device__ __nv_bfloat16 g_Khi[NN * DD];
static __device__ __nv_bfloat16 g_Ethi[DD * NN], g_Etlo[DD * NN];
static __device__ __nv_bfloat16 g_Vthi[DD * NN], g_Vtlo[DD * NN];
static __device__ float g_pos[NN * DD];
static __device__ float g_neg[NN * DD];
static __device__ float g_bnd[NN * DD];
static __device__ float g_agg[NN * DD];

// ---------- baseline-PTX helpers ----------
__device__ __forceinline__ uint32_t smem_u32(const void* p) {
    uint32_t a;
    asm("{ .reg .u64 t; cvta.to.shared.u64 t, %1; cvt.u32.u64 %0, t; }" : "=r"(a) : "l"(p));
    return a;
}
__device__ __forceinline__ void ldsm4(uint32_t& r0, uint32_t& r1, uint32_t& r2, uint32_t& r3,
                                      uint32_t addr) {
    asm volatile("ldmatrix.sync.aligned.m8n8.x4.shared.b16 {%0,%1,%2,%3}, [%4];"
                 : "=r"(r0), "=r"(r1), "=r"(r2), "=r"(r3) : "r"(addr));
}
__device__ __forceinline__ void mma16816(float* c, uint32_t a0, uint32_t a1, uint32_t a2,
                                         uint32_t a3, uint32_t b0, uint32_t b1) {
    asm volatile(
        "mma.sync.aligned.m16n8k16.row.col.f32.bf16.bf16.f32 "
        "{%0,%1,%2,%3},{%4,%5,%6,%7},{%8,%9},{%0,%1,%2,%3};"
        : "+f"(c[0]), "+f"(c[1]), "+f"(c[2]), "+f"(c[3])
        : "r"(a0), "r"(a1), "r"(a2), "r"(a3), "r"(b0), "r"(b1));
}
__device__ __forceinline__ void cpa16(uint32_t saddr, const void* g) {
    asm volatile("cp.async.ca.shared.global [%0], [%1], 16;" :: "r"(saddr), "l"(g));
}
#define CP_COMMIT() asm volatile("cp.async.commit_group;" ::: "memory")
#define CP_WAIT0()  asm volatile("cp.async.wait_group 0;" ::: "memory")
#define CP_WAIT1()  asm volatile("cp.async.wait_group 1;" ::: "memory")

// ---------- small prep ----------
__global__ void init_kernel(const float* __restrict__ emb) {
    int idx = blockIdx.x * 256 + threadIdx.x;
    g_E[idx] = emb[idx];
}
__global__ void adjbits_kernel(const float* __restrict__ adj) {
    int w = blockIdx.x * 256 + threadIdx.x;
    size_t base = (size_t)w * 32;
    unsigned int bits = 0;
    #pragma unroll 8
    for (int b = 0; b < 32; b++) bits |= (adj[base + b] != 0.0f) ? (1u << b) : 0u;
    g_adjbits[w] = bits;
}
// g_any is adjacency-only: compute once (one warp per row)
__global__ void any_kernel() {
    int i = (blockIdx.x * blockDim.x + threadIdx.x) >> 5;
    if (i >= NN) return;
    int lane = threadIdx.x & 31;
    unsigned int v = 0;
    #pragma unroll
    for (int w = 0; w < 8; w++) v |= g_adjbits[i * 256 + lane + w * 32];
    v = __any_sync(0xFFFFFFFFu, v != 0);
    if (lane == 0) g_any[i] = v ? 1.0f : 0.0f;
}
__global__ void zero_flags_kernel() {
    g_flags[blockIdx.x * 256 + threadIdx.x] = 0;
}
// norm + E hi/lo split (one warp per row)
__global__ void norm_kernel() {
    int gw = (blockIdx.x * blockDim.x + threadIdx.x) >> 5;
    if (gw >= NN) return;
    int lane = threadIdx.x & 31;
    size_t o = (size_t)gw * DD + lane * 4;
    float4 v = *(const float4*)(g_E + o);
    float s = v.x * v.x + v.y * v.y + v.z * v.z + v.w * v.w;
    #pragma unroll
    for (int of = 16; of > 0; of >>= 1) s += __shfl_xor_sync(0xFFFFFFFFu, s, of);
    if (lane == 0) g_invnorm[gw] = 1.0f / fmaxf(sqrtf(s), 1e-8f);
    __nv_bfloat16 hx = __float2bfloat16(v.x), hy = __float2bfloat16(v.y);
    __nv_bfloat16 hz = __float2bfloat16(v.z), hw = __float2bfloat16(v.w);
    *(__nv_bfloat162*)(g_Ehi + o)     = __halves2bfloat162(hx, hy);
    *(__nv_bfloat162*)(g_Ehi + o + 2) = __halves2bfloat162(hz, hw);
    *(__nv_bfloat162*)(g_Elo + o) = __halves2bfloat162(
        __float2bfloat16(v.x - __bfloat162float(hx)), __float2bfloat16(v.y - __bfloat162float(hy)));
    *(__nv_bfloat162*)(g_Elo + o + 2) = __halves2bfloat162(
        __float2bfloat16(v.z - __bfloat162float(hz)), __float2bfloat16(v.w - __bfloat162float(hw)));
}

// QKV + direct bf16 writes (Q/K hi only; scores are 1-pass)
__global__ __launch_bounds__(128) void qkv_kernel(
    const float* __restrict__ wq, const float* __restrict__ bq,
    const float* __restrict__ wk, const float* __restrict__ bk,
    const float* __restrict__ wv, const float* __restrict__ bv)
{
    __shared__ float e[8][DD];
    int i0 = blockIdx.x * 8, t = threadIdx.x;
    #pragma unroll
    for (int r = 0; r < 8; r++) e[r][t] = g_E[(size_t)(i0 + r) * DD + t];
    __syncthreads();
    float q[8], k[8], v[8];
    float bqv = bq[t], bkv = bk[t], bvv = bv[t];
    #pragma unroll
    for (int r = 0; r < 8; r++) { q[r] = bqv; k[r] = bkv; v[r] = bvv; }
    #pragma unroll 4
    for (int kk = 0; kk < DD; kk++) {
        float a = wq[kk * DD + t], b = wk[kk * DD + t], c = wv[kk * DD + t];
        #pragma unroll
        for (int r = 0; r < 8; r++) {
            float x = e[r][kk];
            q[r] += x * a; k[r] += x * b; v[r] += x * c;
        }
    }
    #pragma unroll
    for (int r = 0; r < 8; r++) {
        size_t o = (size_t)(i0 + r) * DD + t;
        g_Qhi[o] = __float2bfloat16(q[r]);
        g_Khi[o] = __float2bfloat16(k[r]);
        g_V[o] = v[r];
    }
}

__global__ __launch_bounds__(256) void transpose_split_kernel() {
    __shared__ float te[32][33], tv[32][33];
    int jb = blockIdx.x * 32, db = blockIdx.y * 32;
    int tx = threadIdx.x & 31, ty = threadIdx.x >> 5;
    #pragma unroll
    for (int r = 0; r < 32; r += 8) {
        te[ty + r][tx] = g_E[(size_t)(jb + ty + r) * DD + db + tx];
        tv[ty + r][tx] = g_V[(size_t)(jb + ty + r) * DD + db + tx];
    }
    __syncthreads();
    #pragma unroll
    for (int r = 0; r < 32; r += 8) {
        size_t o = (size_t)(db + ty + r) * NN + jb + tx;
        float e = te[tx][ty + r];
        __nv_bfloat16 h = __float2bfloat16(e);
        g_Ethi[o] = h; g_Etlo[o] = __float2bfloat16(e - __bfloat162float(h));
        float v = tv[tx][ty + r];
        h = __float2bfloat16(v);
        g_Vthi[o] = h; g_Vtlo[o] = __float2bfloat16(v - __bfloat162float(h));
    }
}

// ---------- NT GEMM via mma.sync ----------
// mode0: SIM = (E E^T)*invn_i*invn_j — A0·(B0,B1) merged + A1·B0 (3-pass)
// mode1: P = (Q K^T)/sqrt(D) — single pass A0·B0 (bf16 direct)
__global__ __launch_bounds__(256) void simqk_mma(int mode) {
    extern __shared__ char smem[];
    const int STR = 136;
    const int PLH = 128 * STR;
    __nv_bfloat16* sm = (__nv_bfloat16*)smem;
    const __nv_bfloat16* gA0 = (mode == 0) ? g_Ehi : g_Qhi;
    const __nv_bfloat16* gB0 = (mode == 0) ? g_Ehi : g_Khi;
    float* C = (mode == 0) ? g_SIM : g_P;
    int tid = threadIdx.x;
    int m0 = blockIdx.y * 128, n0 = blockIdx.x * 128;

    for (int idx = tid; idx < 128 * 16; idx += 256) {
        int row = idx >> 4, cg = (idx & 15) * 8;
        size_t gm = (size_t)(m0 + row) * DD + cg;
        size_t gn = (size_t)(n0 + row) * DD + cg;
        int so = row * STR + cg;
        *(uint4*)(sm + 0 * PLH + so) = *(const uint4*)(gA0 + gm);
        *(uint4*)(sm + 2 * PLH + so) = *(const uint4*)(gB0 + gn);
        if (mode == 0) {
            *(uint4*)(sm + 1 * PLH + so) = *(const uint4*)(g_Elo + gm);
            *(uint4*)(sm + 3 * PLH + so) = *(const uint4*)(g_Elo + gn);
        }
    }
    __syncthreads();

    int wid = tid >> 5, lane = tid & 31;
    int wm = wid & 3, wn = wid >> 2;
    uint32_t sb = smem_u32(smem);
    float acc[2][8][4];
    #pragma unroll
    for (int i = 0; i < 2; i++)
        #pragma unroll
        for (int j = 0; j < 8; j++)
            #pragma unroll
            for (int q = 0; q < 4; q++) acc[i][j][q] = 0.0f;

    int a_row = (lane & 15), a_kh = (lane >> 4) * 8;
    int b_row = (lane >> 4) * 8 + (lane & 7), b_kh = ((lane >> 3) & 1) * 8;

    if (mode == 0) {
        // merged pass: A0 x (B0, B1)
        #pragma unroll
        for (int ks = 0; ks < 8; ks++) {
            int k0 = ks * 16;
            uint32_t a[2][4];
            #pragma unroll
            for (int mt = 0; mt < 2; mt++) {
                int row = wm * 32 + mt * 16 + a_row;
                ldsm4(a[mt][0], a[mt][1], a[mt][2], a[mt][3],
                      sb + (uint32_t)(0 * PLH + row * STR + k0 + a_kh) * 2);
            }
            uint32_t b0[8][2], b1[8][2];
            #pragma unroll
            for (int np = 0; np < 4; np++) {
                int row = wn * 64 + np * 16 + b_row;
                ldsm4(b0[np * 2][0], b0[np * 2][1], b0[np * 2 + 1][0], b0[np * 2 + 1][1],
                      sb + (uint32_t)(2 * PLH + row * STR + k0 + b_kh) * 2);
                ldsm4(b1[np * 2][0], b1[np * 2][1], b1[np * 2 + 1][0], b1[np * 2 + 1][1],
                      sb + (uint32_t)(3 * PLH + row * STR + k0 + b_kh) * 2);
            }
            #pragma unroll
            for (int mt = 0; mt < 2; mt++)
                #pragma unroll
                for (int nt = 0; nt < 8; nt++) {
                    mma16816(acc[mt][nt], a[mt][0], a[mt][1], a[mt][2], a[mt][3],
                             b0[nt][0], b0[nt][1]);
                    mma16816(acc[mt][nt], a[mt][0], a[mt][1], a[mt][2], a[mt][3],
                             b1[nt][0], b1[nt][1]);
                }
        }
        // third pass: A1 x B0
        #pragma unroll
        for (int ks = 0; ks < 8; ks++) {
            int k0 = ks * 16;
            uint32_t a[2][4];
            #pragma unroll
            for (int mt = 0; mt < 2; mt++) {
                int row = wm * 32 + mt * 16 + a_row;
                ldsm4(a[mt][0], a[mt][1], a[mt][2], a[mt][3],
                      sb + (uint32_t)(1 * PLH + row * STR + k0 + a_kh) * 2);
            }
            uint32_t b0[8][2];
            #pragma unroll
            for (int np = 0; np < 4; np++) {
                int row = wn * 64 + np * 16 + b_row;
                ldsm4(b0[np * 2][0], b0[np * 2][1], b0[np * 2 + 1][0], b0[np * 2 + 1][1],
                      sb + (uint32_t)(2 * PLH + row * STR + k0 + b_kh) * 2);
            }
            #pragma unroll
            for (int mt = 0; mt < 2; mt++)
                #pragma unroll
                for (int nt = 0; nt < 8; nt++)
                    mma16816(acc[mt][nt], a[mt][0], a[mt][1], a[mt][2], a[mt][3],
                             b0[nt][0], b0[nt][1]);
        }
    } else {
        // single pass: A0 x B0
        #pragma unroll
        for (int ks = 0; ks < 8; ks++) {
            int k0 = ks * 16;
            uint32_t a[2][4];
            #pragma unroll
            for (int mt = 0; mt < 2; mt++) {
                int row = wm * 32 + mt * 16 + a_row;
                ldsm4(a[mt][0], a[mt][1], a[mt][2], a[mt][3],
                      sb + (uint32_t)(0 * PLH + row * STR + k0 + a_kh) * 2);
            }
            uint32_t b0[8][2];
            #pragma unroll
            for (int np = 0; np < 4; np++) {
                int row = wn * 64 + np * 16 + b_row;
                ldsm4(b0[np * 2][0], b0[np * 2][1], b0[np * 2 + 1][0], b0[np * 2 + 1][1],
                      sb + (uint32_t)(2 * PLH + row * STR + k0 + b_kh) * 2);
            }
            #pragma unroll
            for (int mt = 0; mt < 2; mt++)
                #pragma unroll
                for (int nt = 0; nt < 8; nt++)
                    mma16816(acc[mt][nt], a[mt][0], a[mt][1], a[mt][2], a[mt][3],
                             b0[nt][0], b0[nt][1]);
        }
    }

    const float ISD = 0.08838834764831845f;
    int g = lane >> 2, t = lane & 3;
    #pragma unroll
    for (int mt = 0; mt < 2; mt++) {
        int mrow = m0 + wm * 32 + mt * 16 + g;
        float sa0 = (mode == 0) ? g_invnorm[mrow] : ISD;
        float sa1 = (mode == 0) ? g_invnorm[mrow + 8] : ISD;
        #pragma unroll
        for (int nt = 0; nt < 8; nt++) {
            int nc = n0 + wn * 64 + nt * 8 + t * 2;
            float sb0 = (mode == 0) ? g_invnorm[nc] : 1.0f;
            float sb1 = (mode == 0) ? g_invnorm[nc + 1] : 1.0f;
            float* c = acc[mt][nt];
            float2 w0 = { c[0] * sa0 * sb0, c[1] * sa0 * sb1 };
            float2 w1 = { c[2] * sa1 * sb0, c[3] * sa1 * sb1 };
            *(float2*)(C + (size_t)mrow * NN + nc) = w0;
            *(float2*)(C + (size_t)(mrow + 8) * NN + nc) = w1;
        }
    }
}

// ---------- classify + masked softmax + chunk occupancy flags (vectorized) ----------
__device__ __forceinline__ float blk_sum(float v, float* buf) {
    int t = threadIdx.x;
    buf[t] = v; __syncthreads();
    #pragma unroll
    for (int s = 128; s > 0; s >>= 1) { if (t < s) buf[t] += buf[t + s]; __syncthreads(); }
    float r = buf[0]; __syncthreads();
    return r;
}
__device__ __forceinline__ float blk_max(float v, float* buf) {
    int t = threadIdx.x;
    buf[t] = v; __syncthreads();
    #pragma unroll
    for (int s = 128; s > 0; s >>= 1) { if (t < s) buf[t] = fmaxf(buf[t], buf[t + s]); __syncthreads(); }
    float r = buf[0]; __syncthreads();
    return r;
}

__global__ __launch_bounds__(256) void classify_kernel() {
    __shared__ float s2s[NN];
    __shared__ unsigned char cds[NN];
    __shared__ float erow[DD];
    __shared__ float rbuf[256];
    __shared__ unsigned char fl[3][128];
    int i = blockIdx.x, tid = threadIdx.x;
    size_t base = (size_t)i * NN;
    if (tid < DD) erow[tid] = g_E[(size_t)i * DD + tid];
    if (tid < 128) { fl[0][tid] = 0; fl[1][tid] = 0; fl[2][tid] = 0; }
    __syncthreads();
    float inv_i = g_invnorm[i];

    float cp = 0.f, cn = 0.f, mx = -INFINITY;
    for (int j = tid * 4; j < NN; j += 1024) {
        unsigned int w = g_adjbits[i * 256 + (j >> 5)];
        float4 sim4 = *(const float4*)(g_SIM + base + j);
        float4 s4 = *(const float4*)(g_P + base + j);
        float sims[4] = { sim4.x, sim4.y, sim4.z, sim4.w };
        float ss[4] = { s4.x, s4.y, s4.z, s4.w };
        int chunk = j >> 6;
        uchar4 k4;
        unsigned char* kp = (unsigned char*)&k4;
        #pragma unroll
        for (int e = 0; e < 4; e++) {
            int a = (w >> ((j + e) & 31)) & 1;
            int c = 0;
            if (a) {
                float sim = sims[e];
                if (fabsf(sim - ALPHAC) < SIMWIN || fabsf(sim - BETAC) < SIMWIN) {
                    const float* ej = g_E + (size_t)(j + e) * DD;
                    float dot = 0.f;
                    #pragma unroll 4
                    for (int d = 0; d < DD; d++) dot += erow[d] * ej[d];
                    sim = dot * inv_i * g_invnorm[j + e];
                }
                c = (sim >= ALPHAC) ? 1 : ((sim <= BETAC) ? 2 : 3);
                fl[c - 1][chunk] = 1;
                cp += (c == 1) ? 1.0f : 0.0f;
                cn += (c == 2) ? 1.0f : 0.0f;
                if (c == 3) mx = fmaxf(mx, ss[e]);
            }
            kp[e] = (unsigned char)c;
            cds[j + e] = (unsigned char)c;
            s2s[j + e] = ss[e];
        }
        *(uchar4*)(g_code + base + j) = k4;
    }
    cp = blk_sum(cp, rbuf);
    cn = blk_sum(cn, rbuf);
    mx = blk_max(mx, rbuf);
    if (mx == -INFINITY) mx = 0.0f;

    float s = 0.f;
    for (int j = tid * 2; j < NN; j += 512) {
        float e0 = (cds[j] == 3) ? expf(s2s[j] - mx) : 0.0f;
        float e1 = (cds[j + 1] == 3) ? expf(s2s[j + 1] - mx) : 0.0f;
        s2s[j] = e0; s2s[j + 1] = e1;
        s += e0 + e1;
    }
    s = blk_sum(s, rbuf);
    float inv = 1.0f / fmaxf(s, 1e-30f);
    for (int j = tid * 2; j < NN; j += 512) {
        float p0 = s2s[j] * inv, p1 = s2s[j + 1] * inv;
        __nv_bfloat16 h0 = __float2bfloat16(p0), h1 = __float2bfloat16(p1);
        *(__nv_bfloat162*)(g_Phi + base + j) = __halves2bfloat162(h0, h1);
        *(__nv_bfloat162*)(g_Plo + base + j) = __halves2bfloat162(
            __float2bfloat16(p0 - __bfloat162float(h0)),
            __float2bfloat16(p1 - __bfloat162float(h1)));
    }
    int ib = i >> 7;
    if (tid < 128) {
        if (fl[0][tid]) g_flags[0 * 8192 + ib * 128 + tid] = 1;
        if (fl[1][tid]) g_flags[1 * 8192 + ib * 128 + tid] = 1;
        if (fl[2][tid]) g_flags[2 * 8192 + ib * 128 + tid] = 1;
    }
    if (tid == 0) {
        g_invp[i] = 1.0f / fmaxf(cp, 1.0f);
        g_invn[i] = LAMC / fmaxf(cn, 1.0f);
    }
}

// ---------- region GEMMs: chunk skipping + code->mask expansion (unmerged passes) ----------
__global__ __launch_bounds__(256) void region_mma() {
    extern __shared__ char smem[];
    __shared__ int lst[128];
    __shared__ int nch;
    __shared__ unsigned char fl[128];
    const int STR = 72;
    const int PLB = 128 * STR * 2;
    const int STAGE = 4 * PLB;
    const int CODE0 = 2 * STAGE;
    int tid = threadIdx.x;
    int type = blockIdx.x % 3;
    int ib = blockIdx.x / 3;
    int i0 = ib * 128;
    uint32_t sb = smem_u32(smem);

    if (tid < 128) fl[tid] = (unsigned char)g_flags[type * 8192 + ib * 128 + tid];
    __syncthreads();
    if (tid == 0) {
        int n = 0;
        for (int c = 0; c < 128; c++) if (fl[c]) lst[n++] = c;
        nch = n;
    }
    __syncthreads();
    int NCH = nch;

    const __nv_bfloat16* B0 = (type == 2) ? g_Vthi : g_Ethi;
    const __nv_bfloat16* B1 = (type == 2) ? g_Vtlo : g_Etlo;
    int npass = (type == 0) ? 2 : (type == 1) ? 1 : 3;
    unsigned char target = (type == 0) ? 1 : 2;

    int wid = tid >> 5, lane = tid & 31;
    int wm = wid & 3, wn = wid >> 2;
    float acc[2][8][4];
    #pragma unroll
    for (int i = 0; i < 2; i++)
        #pragma unroll
        for (int j = 0; j < 8; j++)
            #pragma unroll
            for (int q = 0; q < 4; q++) acc[i][j][q] = 0.0f;

    int a_row = (lane & 15), a_kh = (lane >> 4) * 8;
    int b_row = (lane >> 4) * 8 + (lane & 7), b_kh = ((lane >> 3) & 1) * 8;
    const int AP[3] = {0, 0, 1}, BP[3] = {2, 3, 2};

    auto load_chunk = [&](int s, int chunkIdx) {
        int j0 = chunkIdx * 64;
        uint32_t st = sb + (uint32_t)(s * STAGE);
        if (type == 2) {
            for (int idx = tid; idx < 1024; idx += 256) {
                int row = idx >> 3, cg = (idx & 7) * 8;
                uint32_t so = (uint32_t)(row * STR + cg) * 2;
                cpa16(st + 0 * PLB + so, g_Phi + (size_t)(i0 + row) * NN + j0 + cg);
                cpa16(st + 1 * PLB + so, g_Plo + (size_t)(i0 + row) * NN + j0 + cg);
                cpa16(st + 2 * PLB + so, B0 + (size_t)row * NN + j0 + cg);
                cpa16(st + 3 * PLB + so, B1 + (size_t)row * NN + j0 + cg);
            }
        } else {
            uint32_t cst = sb + (uint32_t)(CODE0 + s * 8192);
            for (int idx = tid; idx < 512; idx += 256) {
                int row = idx >> 2, cg = (idx & 3) * 16;
                cpa16(cst + (uint32_t)(row * 64 + cg),
                      g_code + (size_t)(i0 + row) * NN + j0 + cg);
            }
            for (int idx = tid; idx < 1024; idx += 256) {
                int row = idx >> 3, cg = (idx & 7) * 8;
                uint32_t so = (uint32_t)(row * STR + cg) * 2;
                cpa16(st + 2 * PLB + so, B0 + (size_t)row * NN + j0 + cg);
                if (type == 0)
                    cpa16(st + 3 * PLB + so, B1 + (size_t)row * NN + j0 + cg);
            }
        }
    };

    if (NCH > 0) {
        load_chunk(0, lst[0]);
        CP_COMMIT();
        for (int ci = 0; ci < NCH; ci++) {
            int s = ci & 1;
            if (ci + 1 < NCH) {
                load_chunk(s ^ 1, lst[ci + 1]);
                CP_COMMIT();
                CP_WAIT1();
            } else {
                CP_WAIT0();
            }
            __syncthreads();

            uint32_t st = sb + (uint32_t)(s * STAGE);
            if (type != 2) {
                const unsigned char* cs =
                    (const unsigned char*)smem + CODE0 + s * 8192 + (tid >> 1) * 64 + (tid & 1) * 32;
                __nv_bfloat16* dst =
                    (__nv_bfloat16*)(smem + s * STAGE) + (tid >> 1) * STR + (tid & 1) * 32;
                const __nv_bfloat16 one = __float2bfloat16(1.0f);
                const __nv_bfloat16 zero = __float2bfloat16(0.0f);
                #pragma unroll
                for (int c = 0; c < 32; c += 2) {
                    *(__nv_bfloat162*)(dst + c) = __halves2bfloat162(
                        (cs[c] == target) ? one : zero,
                        (cs[c + 1] == target) ? one : zero);
                }
                __syncthreads();
            }

            for (int p = 0; p < npass; p++) {
                uint32_t abase = st + (uint32_t)(AP[p] * PLB);
                uint32_t bbase = st + (uint32_t)(BP[p] * PLB);
                #pragma unroll
                for (int ks = 0; ks < 4; ks++) {
                    int k0 = ks * 16;
                    uint32_t a[2][4];
                    #pragma unroll
                    for (int mt = 0; mt < 2; mt++) {
                        int row = wm * 32 + mt * 16 + a_row;
                        ldsm4(a[mt][0], a[mt][1], a[mt][2], a[mt][3],
                              abase + (uint32_t)(row * STR + k0 + a_kh) * 2);
                    }
                    uint32_t b[8][2];
                    #pragma unroll
                    for (int np = 0; np < 4; np++) {
                        int row = wn * 64 + np * 16 + b_row;
                        ldsm4(b[np * 2][0], b[np * 2][1], b[np * 2 + 1][0], b[np * 2 + 1][1],
                              bbase + (uint32_t)(row * STR + k0 + b_kh) * 2);
                    }
                    #pragma unroll
                    for (int mt = 0; mt < 2; mt++)
                        #pragma unroll
                        for (int nt = 0; nt < 8; nt++)
                            mma16816(acc[mt][nt], a[mt][0], a[mt][1], a[mt][2], a[mt][3],
                                     b[nt][0], b[nt][1]);
                }
            }
            __syncthreads();
        }
    }

    float* dst = (type == 0) ? g_pos : (type == 1) ? g_neg : g_bnd;
    int g = lane >> 2, t = lane & 3;
    #pragma unroll
    for (int mt = 0; mt < 2; mt++) {
        int i = i0 + wm * 32 + mt * 16 + g;
        float s0 = (type == 0) ? g_invp[i] : (type == 1) ? g_invn[i] : 1.0f;
        float s1 = (type == 0) ? g_invp[i + 8] : (type == 1) ? g_invn[i + 8] : 1.0f;
        #pragma unroll
        for (int nt = 0; nt < 8; nt++) {
            int d = wn * 64 + nt * 8 + t * 2;
            float* c = acc[mt][nt];
            float2 w0 = { c[0] * s0, c[1] * s0 };
            float2 w1 = { c[2] * s1, c[3] * s1 };
            *(float2*)(dst + (size_t)i * DD + d) = w0;
            *(float2*)(dst + (size_t)(i + 8) * DD + d) = w1;
        }
    }
}

// ---------- gating MLP + fusion ----------
__global__ __launch_bounds__(256) void gate_kernel(
    const float* __restrict__ g1w, const float* __restrict__ g1b,
    const float* __restrict__ g2w, const float* __restrict__ g2b)
{
    __shared__ float x[8][512];
    __shared__ float h[8][257];
    __shared__ float gates[8][4];
    int i0 = blockIdx.x * 8, t = threadIdx.x;

    for (int q = t; q < 8 * 128; q += 256) {
        int r = q >> 7, d = q & 127;
        size_t o = (size_t)(i0 + r) * DD + d;
        x[r][d]       = g_E[o];
        x[r][128 + d] = g_pos[o];
        x[r][256 + d] = g_bnd[o];
        x[r][384 + d] = g_neg[o];
    }
    __syncthreads();

    float acc[8];
    float bb = g1b[t];
    #pragma unroll
    for (int r = 0; r < 8; r++) acc[r] = bb;
    #pragma unroll 4
    for (int kk = 0; kk < 512; kk++) {
        float w = g1w[kk * 256 + t];
        #pragma unroll
        for (int r = 0; r < 8; r++) acc[r] += x[r][kk] * w;
    }
    #pragma unroll
    for (int r = 0; r < 8; r++) h[r][t] = fmaxf(acc[r], 0.0f);
    __syncthreads();

    int wid = t >> 5, lane = t & 31;
    {
        int r = wid;
        float l0 = 0, l1 = 0, l2 = 0, l3 = 0;
        for (int kk = lane; kk < 256; kk += 32) {
            float hv = h[r][kk];
            l0 += hv * g2w[kk * 4 + 0];
            l1 += hv * g2w[kk * 4 + 1];
            l2 += hv * g2w[kk * 4 + 2];
            l3 += hv * g2w[kk * 4 + 3];
        }
        #pragma unroll
        for (int o = 16; o > 0; o >>= 1) {
            l0 += __shfl_xor_sync(0xFFFFFFFFu, l0, o);
            l1 += __shfl_xor_sync(0xFFFFFFFFu, l1, o);
            l2 += __shfl_xor_sync(0xFFFFFFFFu, l2, o);
            l3 += __shfl_xor_sync(0xFFFFFFFFu, l3, o);
        }
        if (lane == 0) {
            l0 += g2b[0]; l1 += g2b[1]; l2 += g2b[2]; l3 += g2b[3];
            float m = fmaxf(fmaxf(l0, l1), fmaxf(l2, l3));
            float e0 = expf(l0 - m), e1 = expf(l1 - m), e2 = expf(l2 - m), e3 = expf(l3 - m);
            float inv = 1.0f / (e0 + e1 + e2 + e3);
            gates[r][0] = e0 * inv; gates[r][1] = e1 * inv;
            gates[r][2] = e2 * inv; gates[r][3] = e3 * inv;
        }
    }
    __syncthreads();

    for (int q = t; q < 8 * 128; q += 256) {
        int r = q >> 7, d = q & 127;
        float any = g_any[i0 + r];
        float f;
        if (any != 0.0f)
            f = gates[r][0] * x[r][d] + gates[r][1] * x[r][128 + d]
              + gates[r][2] * x[r][256 + d] + gates[r][3] * x[r][384 + d];
        else
            f = x[r][d];
        g_agg[(size_t)(i0 + r) * DD + d] = f;
    }
}

// ---------- graph-conv layer + output ----------
__global__ __launch_bounds__(128) void gc_kernel(
    const float* __restrict__ gcw, const float* __restrict__ gcb,
    const float* __restrict__ lwp, int l, float* __restrict__ out)
{
    __shared__ float a[8][DD];
    int i0 = blockIdx.x * 8, t = threadIdx.x;
    #pragma unroll
    for (int r = 0; r < 8; r++) a[r][t] = g_agg[(size_t)(i0 + r) * DD + t];
    __syncthreads();

    float acc[8];
    float b = gcb[t];
    #pragma unroll
    for (int r = 0; r < 8; r++) acc[r] = b;
    #pragma unroll 4
    for (int kk = 0; kk < DD; kk++) {
        float w = gcw[kk * DD + t];
        #pragma unroll
        for (int r = 0; r < 8; r++) acc[r] += a[r][kk] * w;
    }

    float w0 = lwp[0], w1 = lwp[1];
    float m = fmaxf(w0, w1);
    float e0 = expf(w0 - m), e1 = expf(w1 - m);
    float lw = ((l == 0) ? e0 : e1) / (e0 + e1);

    #pragma unroll
    for (int r = 0; r < 8; r++) {
        float v = fmaxf(acc[r], 0.0f);
        size_t o = (size_t)(i0 + r) * DD + t;
        g_E[o] = v;
        if (l == 0) out[o] = lw * v;
        else        out[o] += lw * v;
    }
}

extern "C" void kernel_launch(void* const* d_in, const int* in_sizes, int n_in,
                              void* d_out, int out_size)
{
    const float* adj  = (const float*)d_in[0];
    const float* emb  = (const float*)d_in[1];
    const float* gc_w = (const float*)d_in[2];
    const float* gc_b = (const float*)d_in[3];
    const float* wq   = (const float*)d_in[4];
    const float* bq   = (const float*)d_in[5];
    const float* wk   = (const float*)d_in[6];
    const float* bk   = (const float*)d_in[7];
    const float* wv   = (const float*)d_in[8];
    const float* bv   = (const float*)d_in[9];
    const float* g1w  = (const float*)d_in[10];
    const float* g1b  = (const float*)d_in[11];
    const float* g2w  = (const float*)d_in[12];
    const float* g2b  = (const float*)d_in[13];
    const float* lw   = (const float*)d_in[14];
    float* out = (float*)d_out;

    const int simqk_smem  = 4 * 128 * 136 * 2;                 // 139264
    const int region_smem = 2 * 4 * 128 * 72 * 2 + 2 * 8192;   // 163840
    cudaFuncSetAttribute(simqk_mma, cudaFuncAttributeMaxDynamicSharedMemorySize, simqk_smem);
    cudaFuncSetAttribute(region_mma, cudaFuncAttributeMaxDynamicSharedMemorySize, region_smem);

    init_kernel<<<(NN * DD) / 256, 256>>>(emb);
    adjbits_kernel<<<(NN * NN / 32) / 256, 256>>>(adj);
    any_kernel<<<NN * 32 / 256, 256>>>();

    for (int l = 0; l < 2; l++) {
        norm_kernel<<<NN * 32 / 256, 256>>>();
        qkv_kernel<<<NN / 8, 128>>>(wq, bq, wk, bk, wv, bv);
        transpose_split_kernel<<<dim3(NN / 32, DD / 32), 256>>>();
        simqk_mma<<<dim3(64, 64), 256, simqk_smem>>>(0);
        simqk_mma<<<dim3(64, 64), 256, simqk_smem>>>(1);
        zero_flags_kernel<<<(3 * 64 * 128) / 256, 256>>>();
        classify_kernel<<<NN, 256>>>();
        region_mma<<<3 * (NN / 128), 256, region_smem>>>();
        gate_kernel<<<NN / 8, 256>>>(g1w, g1b, g2w, g2b);
        gc_kernel<<<NN / 8, 128>>>(gc_w + (size_t)l * DD * DD, gc_b + (size_t)l * DD,
                                   lw, l, out);
    }
}

// round 16
// speedup vs baseline: 1.2614x; 1.0111x over previous
#include <cuda_runtime.h>
#include <cuda_bf16.h>
#include <math.h>
#include <stdint.h>

#define NN 8192
#define DD 128
#define ALPHAC 0.7f
#define BETAC  0.3f
#define LAMC   0.1f
#define SIMWIN 1e-4f

static __device__ float g_E[NN * DD];
static __device__ float g_V[NN * DD];
static __device__ float g_invnorm[NN];
static __device__ float g_invp[NN];
static __device__ float g_invn[NN];
static __device__ float g_any[NN];
static __device__ float g_SIM[(size_t)NN * NN];                // sim (fp32)
static __device__ __nv_bfloat16 g_Pb[(size_t)NN * NN];         // attn scores (bf16)
static __device__ unsigned char g_code[(size_t)NN * NN];       // region code 0..3
static __device__ __nv_bfloat16 g_Phi[(size_t)NN * NN];
static __device__ __nv_bfloat16 g_Plo[(size_t)NN * NN];
static __device__ unsigned int g_adjbits[NN * NN / 32];
static __device__ int g_flags[3 * 64 * 128];                   // [type][iblock][jchunk]
static __device__ __nv_bfloat16 g_Ehi[NN * DD], g_Elo[NN * DD];
static __device__ __nv_bfloat16 g_Qhi[NN * DD];
static __device__ __nv_bfloat16 g_Khi[NN * DD];
static __device__ __nv_bfloat16 g_Ethi[DD * NN], g_Etlo[DD * NN];
static __device__ __nv_bfloat16 g_Vthi[DD * NN], g_Vtlo[DD * NN];
static __device__ float g_pos[NN * DD];
static __device__ float g_neg[NN * DD];
static __device__ float g_bnd[NN * DD];
static __device__ float g_agg[NN * DD];

// ---------- baseline-PTX helpers ----------
__device__ __forceinline__ uint32_t smem_u32(const void* p) {
    uint32_t a;
    asm("{ .reg .u64 t; cvta.to.shared.u64 t, %1; cvt.u32.u64 %0, t; }" : "=r"(a) : "l"(p));
    return a;
}
__device__ __forceinline__ void ldsm4(uint32_t& r0, uint32_t& r1, uint32_t& r2, uint32_t& r3,
                                      uint32_t addr) {
    asm volatile("ldmatrix.sync.aligned.m8n8.x4.shared.b16 {%0,%1,%2,%3}, [%4];"
                 : "=r"(r0), "=r"(r1), "=r"(r2), "=r"(r3) : "r"(addr));
}
__device__ __forceinline__ void mma16816(float* c, uint32_t a0, uint32_t a1, uint32_t a2,
                                         uint32_t a3, uint32_t b0, uint32_t b1) {
    asm volatile(
        "mma.sync.aligned.m16n8k16.row.col.f32.bf16.bf16.f32 "
        "{%0,%1,%2,%3},{%4,%5,%6,%7},{%8,%9},{%0,%1,%2,%3};"
        : "+f"(c[0]), "+f"(c[1]), "+f"(c[2]), "+f"(c[3])
        : "r"(a0), "r"(a1), "r"(a2), "r"(a3), "r"(b0), "r"(b1));
}
__device__ __forceinline__ void cpa16(uint32_t saddr, const void* g) {
    asm volatile("cp.async.ca.shared.global [%0], [%1], 16;" :: "r"(saddr), "l"(g));
}
#define CP_COMMIT() asm volatile("cp.async.commit_group;" ::: "memory")
#define CP_WAIT0()  asm volatile("cp.async.wait_group 0;" ::: "memory")
#define CP_WAIT1()  asm volatile("cp.async.wait_group 1;" ::: "memory")

// ---------- small prep ----------
__global__ void init_kernel(const float* __restrict__ emb) {
    int idx = blockIdx.x * 256 + threadIdx.x;
    g_E[idx] = emb[idx];
}
__global__ void adjbits_kernel(const float* __restrict__ adj) {
    int w = blockIdx.x * 256 + threadIdx.x;
    size_t base = (size_t)w * 32;
    unsigned int bits = 0;
    #pragma unroll 8
    for (int b = 0; b < 32; b++) bits |= (adj[base + b] != 0.0f) ? (1u << b) : 0u;
    g_adjbits[w] = bits;
}
// g_any is adjacency-only: compute once (one warp per row)
__global__ void any_kernel() {
    int i = (blockIdx.x * blockDim.x + threadIdx.x) >> 5;
    if (i >= NN) return;
    int lane = threadIdx.x & 31;
    unsigned int v = 0;
    #pragma unroll
    for (int w = 0; w < 8; w++) v |= g_adjbits[i * 256 + lane + w * 32];
    v = __any_sync(0xFFFFFFFFu, v != 0);
    if (lane == 0) g_any[i] = v ? 1.0f : 0.0f;
}
__global__ void zero_flags_kernel() {
    g_flags[blockIdx.x * 256 + threadIdx.x] = 0;
}
// norm + E hi/lo split (one warp per row)
__global__ void norm_kernel() {
    int gw = (blockIdx.x * blockDim.x + threadIdx.x) >> 5;
    if (gw >= NN) return;
    int lane = threadIdx.x & 31;
    size_t o = (size_t)gw * DD + lane * 4;
    float4 v = *(const float4*)(g_E + o);
    float s = v.x * v.x + v.y * v.y + v.z * v.z + v.w * v.w;
    #pragma unroll
    for (int of = 16; of > 0; of >>= 1) s += __shfl_xor_sync(0xFFFFFFFFu, s, of);
    if (lane == 0) g_invnorm[gw] = 1.0f / fmaxf(sqrtf(s), 1e-8f);
    __nv_bfloat16 hx = __float2bfloat16(v.x), hy = __float2bfloat16(v.y);
    __nv_bfloat16 hz = __float2bfloat16(v.z), hw = __float2bfloat16(v.w);
    *(__nv_bfloat162*)(g_Ehi + o)     = __halves2bfloat162(hx, hy);
    *(__nv_bfloat162*)(g_Ehi + o + 2) = __halves2bfloat162(hz, hw);
    *(__nv_bfloat162*)(g_Elo + o) = __halves2bfloat162(
        __float2bfloat16(v.x - __bfloat162float(hx)), __float2bfloat16(v.y - __bfloat162float(hy)));
    *(__nv_bfloat162*)(g_Elo + o + 2) = __halves2bfloat162(
        __float2bfloat16(v.z - __bfloat162float(hz)), __float2bfloat16(v.w - __bfloat162float(hw)));
}

// QKV + direct bf16 writes (Q/K hi only; scores are 1-pass)
__global__ __launch_bounds__(128) void qkv_kernel(
    const float* __restrict__ wq, const float* __restrict__ bq,
    const float* __restrict__ wk, const float* __restrict__ bk,
    const float* __restrict__ wv, const float* __restrict__ bv)
{
    __shared__ float e[8][DD];
    int i0 = blockIdx.x * 8, t = threadIdx.x;
    #pragma unroll
    for (int r = 0; r < 8; r++) e[r][t] = g_E[(size_t)(i0 + r) * DD + t];
    __syncthreads();
    float q[8], k[8], v[8];
    float bqv = bq[t], bkv = bk[t], bvv = bv[t];
    #pragma unroll
    for (int r = 0; r < 8; r++) { q[r] = bqv; k[r] = bkv; v[r] = bvv; }
    #pragma unroll 4
    for (int kk = 0; kk < DD; kk++) {
        float a = wq[kk * DD + t], b = wk[kk * DD + t], c = wv[kk * DD + t];
        #pragma unroll
        for (int r = 0; r < 8; r++) {
            float x = e[r][kk];
            q[r] += x * a; k[r] += x * b; v[r] += x * c;
        }
    }
    #pragma unroll
    for (int r = 0; r < 8; r++) {
        size_t o = (size_t)(i0 + r) * DD + t;
        g_Qhi[o] = __float2bfloat16(q[r]);
        g_Khi[o] = __float2bfloat16(k[r]);
        g_V[o] = v[r];
    }
}

__global__ __launch_bounds__(256) void transpose_split_kernel() {
    __shared__ float te[32][33], tv[32][33];
    int jb = blockIdx.x * 32, db = blockIdx.y * 32;
    int tx = threadIdx.x & 31, ty = threadIdx.x >> 5;
    #pragma unroll
    for (int r = 0; r < 32; r += 8) {
        te[ty + r][tx] = g_E[(size_t)(jb + ty + r) * DD + db + tx];
        tv[ty + r][tx] = g_V[(size_t)(jb + ty + r) * DD + db + tx];
    }
    __syncthreads();
    #pragma unroll
    for (int r = 0; r < 32; r += 8) {
        size_t o = (size_t)(db + ty + r) * NN + jb + tx;
        float e = te[tx][ty + r];
        __nv_bfloat16 h = __float2bfloat16(e);
        g_Ethi[o] = h; g_Etlo[o] = __float2bfloat16(e - __bfloat162float(h));
        float v = tv[tx][ty + r];
        h = __float2bfloat16(v);
        g_Vthi[o] = h; g_Vtlo[o] = __float2bfloat16(v - __bfloat162float(h));
    }
}

// ---------- NT GEMM via mma.sync ----------
// mode0: SIM = (E E^T)*invn_i*invn_j — A0·(B0,B1) merged + A1·B0 (3-pass), fp32 out
// mode1: P = (Q K^T)/sqrt(D) — single pass A0·B0, bf16 out
__global__ __launch_bounds__(256) void simqk_mma(int mode) {
    extern __shared__ char smem[];
    const int STR = 136;
    const int PLH = 128 * STR;
    __nv_bfloat16* sm = (__nv_bfloat16*)smem;
    const __nv_bfloat16* gA0 = (mode == 0) ? g_Ehi : g_Qhi;
    const __nv_bfloat16* gB0 = (mode == 0) ? g_Ehi : g_Khi;
    int tid = threadIdx.x;
    int m0 = blockIdx.y * 128, n0 = blockIdx.x * 128;

    for (int idx = tid; idx < 128 * 16; idx += 256) {
        int row = idx >> 4, cg = (idx & 15) * 8;
        size_t gm = (size_t)(m0 + row) * DD + cg;
        size_t gn = (size_t)(n0 + row) * DD + cg;
        int so = row * STR + cg;
        *(uint4*)(sm + 0 * PLH + so) = *(const uint4*)(gA0 + gm);
        *(uint4*)(sm + 2 * PLH + so) = *(const uint4*)(gB0 + gn);
        if (mode == 0) {
            *(uint4*)(sm + 1 * PLH + so) = *(const uint4*)(g_Elo + gm);
            *(uint4*)(sm + 3 * PLH + so) = *(const uint4*)(g_Elo + gn);
        }
    }
    __syncthreads();

    int wid = tid >> 5, lane = tid & 31;
    int wm = wid & 3, wn = wid >> 2;
    uint32_t sb = smem_u32(smem);
    float acc[2][8][4];
    #pragma unroll
    for (int i = 0; i < 2; i++)
        #pragma unroll
        for (int j = 0; j < 8; j++)
            #pragma unroll
            for (int q = 0; q < 4; q++) acc[i][j][q] = 0.0f;

    int a_row = (lane & 15), a_kh = (lane >> 4) * 8;
    int b_row = (lane >> 4) * 8 + (lane & 7), b_kh = ((lane >> 3) & 1) * 8;

    if (mode == 0) {
        #pragma unroll
        for (int ks = 0; ks < 8; ks++) {
            int k0 = ks * 16;
            uint32_t a[2][4];
            #pragma unroll
            for (int mt = 0; mt < 2; mt++) {
                int row = wm * 32 + mt * 16 + a_row;
                ldsm4(a[mt][0], a[mt][1], a[mt][2], a[mt][3],
                      sb + (uint32_t)(0 * PLH + row * STR + k0 + a_kh) * 2);
            }
            uint32_t b0[8][2], b1[8][2];
            #pragma unroll
            for (int np = 0; np < 4; np++) {
                int row = wn * 64 + np * 16 + b_row;
                ldsm4(b0[np * 2][0], b0[np * 2][1], b0[np * 2 + 1][0], b0[np * 2 + 1][1],
                      sb + (uint32_t)(2 * PLH + row * STR + k0 + b_kh) * 2);
                ldsm4(b1[np * 2][0], b1[np * 2][1], b1[np * 2 + 1][0], b1[np * 2 + 1][1],
                      sb + (uint32_t)(3 * PLH + row * STR + k0 + b_kh) * 2);
            }
            #pragma unroll
            for (int mt = 0; mt < 2; mt++)
                #pragma unroll
                for (int nt = 0; nt < 8; nt++) {
                    mma16816(acc[mt][nt], a[mt][0], a[mt][1], a[mt][2], a[mt][3],
                             b0[nt][0], b0[nt][1]);
                    mma16816(acc[mt][nt], a[mt][0], a[mt][1], a[mt][2], a[mt][3],
                             b1[nt][0], b1[nt][1]);
                }
        }
        #pragma unroll
        for (int ks = 0; ks < 8; ks++) {
            int k0 = ks * 16;
            uint32_t a[2][4];
            #pragma unroll
            for (int mt = 0; mt < 2; mt++) {
                int row = wm * 32 + mt * 16 + a_row;
                ldsm4(a[mt][0], a[mt][1], a[mt][2], a[mt][3],
                      sb + (uint32_t)(1 * PLH + row * STR + k0 + a_kh) * 2);
            }
            uint32_t b0[8][2];
            #pragma unroll
            for (int np = 0; np < 4; np++) {
                int row = wn * 64 + np * 16 + b_row;
                ldsm4(b0[np * 2][0], b0[np * 2][1], b0[np * 2 + 1][0], b0[np * 2 + 1][1],
                      sb + (uint32_t)(2 * PLH + row * STR + k0 + b_kh) * 2);
            }
            #pragma unroll
            for (int mt = 0; mt < 2; mt++)
                #pragma unroll
                for (int nt = 0; nt < 8; nt++)
                    mma16816(acc[mt][nt], a[mt][0], a[mt][1], a[mt][2], a[mt][3],
                             b0[nt][0], b0[nt][1]);
        }
    } else {
        #pragma unroll
        for (int ks = 0; ks < 8; ks++) {
            int k0 = ks * 16;
            uint32_t a[2][4];
            #pragma unroll
            for (int mt = 0; mt < 2; mt++) {
                int row = wm * 32 + mt * 16 + a_row;
                ldsm4(a[mt][0], a[mt][1], a[mt][2], a[mt][3],
                      sb + (uint32_t)(0 * PLH + row * STR + k0 + a_kh) * 2);
            }
            uint32_t b0[8][2];
            #pragma unroll
            for (int np = 0; np < 4; np++) {
                int row = wn * 64 + np * 16 + b_row;
                ldsm4(b0[np * 2][0], b0[np * 2][1], b0[np * 2 + 1][0], b0[np * 2 + 1][1],
                      sb + (uint32_t)(2 * PLH + row * STR + k0 + b_kh) * 2);
            }
            #pragma unroll
            for (int mt = 0; mt < 2; mt++)
                #pragma unroll
                for (int nt = 0; nt < 8; nt++)
                    mma16816(acc[mt][nt], a[mt][0], a[mt][1], a[mt][2], a[mt][3],
                             b0[nt][0], b0[nt][1]);
        }
    }

    const float ISD = 0.08838834764831845f;
    int g = lane >> 2, t = lane & 3;
    #pragma unroll
    for (int mt = 0; mt < 2; mt++) {
        int mrow = m0 + wm * 32 + mt * 16 + g;
        #pragma unroll
        for (int nt = 0; nt < 8; nt++) {
            int nc = n0 + wn * 64 + nt * 8 + t * 2;
            float* c = acc[mt][nt];
            if (mode == 0) {
                float sa0 = g_invnorm[mrow], sa1 = g_invnorm[mrow + 8];
                float sb0 = g_invnorm[nc], sb1 = g_invnorm[nc + 1];
                float2 w0 = { c[0] * sa0 * sb0, c[1] * sa0 * sb1 };
                float2 w1 = { c[2] * sa1 * sb0, c[3] * sa1 * sb1 };
                *(float2*)(g_SIM + (size_t)mrow * NN + nc) = w0;
                *(float2*)(g_SIM + (size_t)(mrow + 8) * NN + nc) = w1;
            } else {
                *(__nv_bfloat162*)(g_Pb + (size_t)mrow * NN + nc) =
                    __halves2bfloat162(__float2bfloat16(c[0] * ISD),
                                       __float2bfloat16(c[1] * ISD));
                *(__nv_bfloat162*)(g_Pb + (size_t)(mrow + 8) * NN + nc) =
                    __halves2bfloat162(__float2bfloat16(c[2] * ISD),
                                       __float2bfloat16(c[3] * ISD));
            }
        }
    }
}

// ---------- classify + masked softmax + chunk occupancy flags (vectorized) ----------
__device__ __forceinline__ float blk_sum(float v, float* buf) {
    int t = threadIdx.x;
    buf[t] = v; __syncthreads();
    #pragma unroll
    for (int s = 128; s > 0; s >>= 1) { if (t < s) buf[t] += buf[t + s]; __syncthreads(); }
    float r = buf[0]; __syncthreads();
    return r;
}
__device__ __forceinline__ float blk_max(float v, float* buf) {
    int t = threadIdx.x;
    buf[t] = v; __syncthreads();
    #pragma unroll
    for (int s = 128; s > 0; s >>= 1) { if (t < s) buf[t] = fmaxf(buf[t], buf[t + s]); __syncthreads(); }
    float r = buf[0]; __syncthreads();
    return r;
}

__global__ __launch_bounds__(256) void classify_kernel() {
    __shared__ float s2s[NN];
    __shared__ unsigned char cds[NN];
    __shared__ float erow[DD];
    __shared__ float rbuf[256];
    __shared__ unsigned char fl[3][128];
    int i = blockIdx.x, tid = threadIdx.x;
    size_t base = (size_t)i * NN;
    if (tid < DD) erow[tid] = g_E[(size_t)i * DD + tid];
    if (tid < 128) { fl[0][tid] = 0; fl[1][tid] = 0; fl[2][tid] = 0; }
    __syncthreads();
    float inv_i = g_invnorm[i];

    float cp = 0.f, cn = 0.f, mx = -INFINITY;
    for (int j = tid * 4; j < NN; j += 1024) {
        unsigned int w = g_adjbits[i * 256 + (j >> 5)];
        float4 sim4 = *(const float4*)(g_SIM + base + j);
        __nv_bfloat162 p01 = *(const __nv_bfloat162*)(g_Pb + base + j);
        __nv_bfloat162 p23 = *(const __nv_bfloat162*)(g_Pb + base + j + 2);
        float sims[4] = { sim4.x, sim4.y, sim4.z, sim4.w };
        float ss[4] = { __bfloat162float(__low2bfloat16(p01)),
                        __bfloat162float(__high2bfloat16(p01)),
                        __bfloat162float(__low2bfloat16(p23)),
                        __bfloat162float(__high2bfloat16(p23)) };
        int chunk = j >> 6;
        uchar4 k4;
        unsigned char* kp = (unsigned char*)&k4;
        #pragma unroll
        for (int e = 0; e < 4; e++) {
            int a = (w >> ((j + e) & 31)) & 1;
            int c = 0;
            if (a) {
                float sim = sims[e];
                if (fabsf(sim - ALPHAC) < SIMWIN || fabsf(sim - BETAC) < SIMWIN) {
                    const float* ej = g_E + (size_t)(j + e) * DD;
                    float dot = 0.f;
                    #pragma unroll 4
                    for (int d = 0; d < DD; d++) dot += erow[d] * ej[d];
                    sim = dot * inv_i * g_invnorm[j + e];
                }
                c = (sim >= ALPHAC) ? 1 : ((sim <= BETAC) ? 2 : 3);
                fl[c - 1][chunk] = 1;
                cp += (c == 1) ? 1.0f : 0.0f;
                cn += (c == 2) ? 1.0f : 0.0f;
                if (c == 3) mx = fmaxf(mx, ss[e]);
            }
            kp[e] = (unsigned char)c;
            cds[j + e] = (unsigned char)c;
            s2s[j + e] = ss[e];
        }
        *(uchar4*)(g_code + base + j) = k4;
    }
    cp = blk_sum(cp, rbuf);
    cn = blk_sum(cn, rbuf);
    mx = blk_max(mx, rbuf);
    if (mx == -INFINITY) mx = 0.0f;

    float s = 0.f;
    for (int j = tid * 2; j < NN; j += 512) {
        float e0 = (cds[j] == 3) ? expf(s2s[j] - mx) : 0.0f;
        float e1 = (cds[j + 1] == 3) ? expf(s2s[j + 1] - mx) : 0.0f;
        s2s[j] = e0; s2s[j + 1] = e1;
        s += e0 + e1;
    }
    s = blk_sum(s, rbuf);
    float inv = 1.0f / fmaxf(s, 1e-30f);
    for (int j = tid * 2; j < NN; j += 512) {
        float p0 = s2s[j] * inv, p1 = s2s[j + 1] * inv;
        __nv_bfloat16 h0 = __float2bfloat16(p0), h1 = __float2bfloat16(p1);
        *(__nv_bfloat162*)(g_Phi + base + j) = __halves2bfloat162(h0, h1);
        *(__nv_bfloat162*)(g_Plo + base + j) = __halves2bfloat162(
            __float2bfloat16(p0 - __bfloat162float(h0)),
            __float2bfloat16(p1 - __bfloat162float(h1)));
    }
    int ib = i >> 7;
    if (tid < 128) {
        if (fl[0][tid]) g_flags[0 * 8192 + ib * 128 + tid] = 1;
        if (fl[1][tid]) g_flags[1 * 8192 + ib * 128 + tid] = 1;
        if (fl[2][tid]) g_flags[2 * 8192 + ib * 128 + tid] = 1;
    }
    if (tid == 0) {
        g_invp[i] = 1.0f / fmaxf(cp, 1.0f);
        g_invn[i] = LAMC / fmaxf(cn, 1.0f);
    }
}

// ---------- region GEMMs: chunk skipping + code->mask expansion (unmerged passes) ----------
__global__ __launch_bounds__(256) void region_mma() {
    extern __shared__ char smem[];
    __shared__ int lst[128];
    __shared__ int nch;
    __shared__ unsigned char fl[128];
    const int STR = 72;
    const int PLB = 128 * STR * 2;
    const int STAGE = 4 * PLB;
    const int CODE0 = 2 * STAGE;
    int tid = threadIdx.x;
    int type = blockIdx.x % 3;
    int ib = blockIdx.x / 3;
    int i0 = ib * 128;
    uint32_t sb = smem_u32(smem);

    if (tid < 128) fl[tid] = (unsigned char)g_flags[type * 8192 + ib * 128 + tid];
    __syncthreads();
    if (tid == 0) {
        int n = 0;
        for (int c = 0; c < 128; c++) if (fl[c]) lst[n++] = c;
        nch = n;
    }
    __syncthreads();
    int NCH = nch;

    const __nv_bfloat16* B0 = (type == 2) ? g_Vthi : g_Ethi;
    const __nv_bfloat16* B1 = (type == 2) ? g_Vtlo : g_Etlo;
    int npass = (type == 0) ? 2 : (type == 1) ? 1 : 3;
    unsigned char target = (type == 0) ? 1 : 2;

    int wid = tid >> 5, lane = tid & 31;
    int wm = wid & 3, wn = wid >> 2;
    float acc[2][8][4];
    #pragma unroll
    for (int i = 0; i < 2; i++)
        #pragma unroll
        for (int j = 0; j < 8; j++)
            #pragma unroll
            for (int q = 0; q < 4; q++) acc[i][j][q] = 0.0f;

    int a_row = (lane & 15), a_kh = (lane >> 4) * 8;
    int b_row = (lane >> 4) * 8 + (lane & 7), b_kh = ((lane >> 3) & 1) * 8;
    const int AP[3] = {0, 0, 1}, BP[3] = {2, 3, 2};

    auto load_chunk = [&](int s, int chunkIdx) {
        int j0 = chunkIdx * 64;
        uint32_t st = sb + (uint32_t)(s * STAGE);
        if (type == 2) {
            for (int idx = tid; idx < 1024; idx += 256) {
                int row = idx >> 3, cg = (idx & 7) * 8;
                uint32_t so = (uint32_t)(row * STR + cg) * 2;
                cpa16(st + 0 * PLB + so, g_Phi + (size_t)(i0 + row) * NN + j0 + cg);
                cpa16(st + 1 * PLB + so, g_Plo + (size_t)(i0 + row) * NN + j0 + cg);
                cpa16(st + 2 * PLB + so, B0 + (size_t)row * NN + j0 + cg);
                cpa16(st + 3 * PLB + so, B1 + (size_t)row * NN + j0 + cg);
            }
        } else {
            uint32_t cst = sb + (uint32_t)(CODE0 + s * 8192);
            for (int idx = tid; idx < 512; idx += 256) {
                int row = idx >> 2, cg = (idx & 3) * 16;
                cpa16(cst + (uint32_t)(row * 64 + cg),
                      g_code + (size_t)(i0 + row) * NN + j0 + cg);
            }
            for (int idx = tid; idx < 1024; idx += 256) {
                int row = idx >> 3, cg = (idx & 7) * 8;
                uint32_t so = (uint32_t)(row * STR + cg) * 2;
                cpa16(st + 2 * PLB + so, B0 + (size_t)row * NN + j0 + cg);
                if (type == 0)
                    cpa16(st + 3 * PLB + so, B1 + (size_t)row * NN + j0 + cg);
            }
        }
    };

    if (NCH > 0) {
        load_chunk(0, lst[0]);
        CP_COMMIT();
        for (int ci = 0; ci < NCH; ci++) {
            int s = ci & 1;
            if (ci + 1 < NCH) {
                load_chunk(s ^ 1, lst[ci + 1]);
                CP_COMMIT();
                CP_WAIT1();
            } else {
                CP_WAIT0();
            }
            __syncthreads();

            uint32_t st = sb + (uint32_t)(s * STAGE);
            if (type != 2) {
                const unsigned char* cs =
                    (const unsigned char*)smem + CODE0 + s * 8192 + (tid >> 1) * 64 + (tid & 1) * 32;
                __nv_bfloat16* dst =
                    (__nv_bfloat16*)(smem + s * STAGE) + (tid >> 1) * STR + (tid & 1) * 32;
                const __nv_bfloat16 one = __float2bfloat16(1.0f);
                const __nv_bfloat16 zero = __float2bfloat16(0.0f);
                #pragma unroll
                for (int c = 0; c < 32; c += 2) {
                    *(__nv_bfloat162*)(dst + c) = __halves2bfloat162(
                        (cs[c] == target) ? one : zero,
                        (cs[c + 1] == target) ? one : zero);
                }
                __syncthreads();
            }

            for (int p = 0; p < npass; p++) {
                uint32_t abase = st + (uint32_t)(AP[p] * PLB);
                uint32_t bbase = st + (uint32_t)(BP[p] * PLB);
                #pragma unroll
                for (int ks = 0; ks < 4; ks++) {
                    int k0 = ks * 16;
                    uint32_t a[2][4];
                    #pragma unroll
                    for (int mt = 0; mt < 2; mt++) {
                        int row = wm * 32 + mt * 16 + a_row;
                        ldsm4(a[mt][0], a[mt][1], a[mt][2], a[mt][3],
                              abase + (uint32_t)(row * STR + k0 + a_kh) * 2);
                    }
                    uint32_t b[8][2];
                    #pragma unroll
                    for (int np = 0; np < 4; np++) {
                        int row = wn * 64 + np * 16 + b_row;
                        ldsm4(b[np * 2][0], b[np * 2][1], b[np * 2 + 1][0], b[np * 2 + 1][1],
                              bbase + (uint32_t)(row * STR + k0 + b_kh) * 2);
                    }
                    #pragma unroll
                    for (int mt = 0; mt < 2; mt++)
                        #pragma unroll
                        for (int nt = 0; nt < 8; nt++)
                            mma16816(acc[mt][nt], a[mt][0], a[mt][1], a[mt][2], a[mt][3],
                                     b[nt][0], b[nt][1]);
                }
            }
            __syncthreads();
        }
    }

    float* dst = (type == 0) ? g_pos : (type == 1) ? g_neg : g_bnd;
    int g = lane >> 2, t = lane & 3;
    #pragma unroll
    for (int mt = 0; mt < 2; mt++) {
        int i = i0 + wm * 32 + mt * 16 + g;
        float s0 = (type == 0) ? g_invp[i] : (type == 1) ? g_invn[i] : 1.0f;
        float s1 = (type == 0) ? g_invp[i + 8] : (type == 1) ? g_invn[i + 8] : 1.0f;
        #pragma unroll
        for (int nt = 0; nt < 8; nt++) {
            int d = wn * 64 + nt * 8 + t * 2;
            float* c = acc[mt][nt];
            float2 w0 = { c[0] * s0, c[1] * s0 };
            float2 w1 = { c[2] * s1, c[3] * s1 };
            *(float2*)(dst + (size_t)i * DD + d) = w0;
            *(float2*)(dst + (size_t)(i + 8) * DD + d) = w1;
        }
    }
}

// ---------- gating MLP + fusion ----------
__global__ __launch_bounds__(256) void gate_kernel(
    const float* __restrict__ g1w, const float* __restrict__ g1b,
    const float* __restrict__ g2w, const float* __restrict__ g2b)
{
    __shared__ float x[8][512];
    __shared__ float h[8][257];
    __shared__ float gates[8][4];
    int i0 = blockIdx.x * 8, t = threadIdx.x;

    for (int q = t; q < 8 * 128; q += 256) {
        int r = q >> 7, d = q & 127;
        size_t o = (size_t)(i0 + r) * DD + d;
        x[r][d]       = g_E[o];
        x[r][128 + d] = g_pos[o];
        x[r][256 + d] = g_bnd[o];
        x[r][384 + d] = g_neg[o];
    }
    __syncthreads();

    float acc[8];
    float bb = g1b[t];
    #pragma unroll
    for (int r = 0; r < 8; r++) acc[r] = bb;
    #pragma unroll 4
    for (int kk = 0; kk < 512; kk++) {
        float w = g1w[kk * 256 + t];
        #pragma unroll
        for (int r = 0; r < 8; r++) acc[r] += x[r][kk] * w;
    }
    #pragma unroll
    for (int r = 0; r < 8; r++) h[r][t] = fmaxf(acc[r], 0.0f);
    __syncthreads();

    int wid = t >> 5, lane = t & 31;
    {
        int r = wid;
        float l0 = 0, l1 = 0, l2 = 0, l3 = 0;
        for (int kk = lane; kk < 256; kk += 32) {
            float hv = h[r][kk];
            l0 += hv * g2w[kk * 4 + 0];
            l1 += hv * g2w[kk * 4 + 1];
            l2 += hv * g2w[kk * 4 + 2];
            l3 += hv * g2w[kk * 4 + 3];
        }
        #pragma unroll
        for (int o = 16; o > 0; o >>= 1) {
            l0 += __shfl_xor_sync(0xFFFFFFFFu, l0, o);
            l1 += __shfl_xor_sync(0xFFFFFFFFu, l1, o);
            l2 += __shfl_xor_sync(0xFFFFFFFFu, l2, o);
            l3 += __shfl_xor_sync(0xFFFFFFFFu, l3, o);
        }
        if (lane == 0) {
            l0 += g2b[0]; l1 += g2b[1]; l2 += g2b[2]; l3 += g2b[3];
            float m = fmaxf(fmaxf(l0, l1), fmaxf(l2, l3));
            float e0 = expf(l0 - m), e1 = expf(l1 - m), e2 = expf(l2 - m), e3 = expf(l3 - m);
            float inv = 1.0f / (e0 + e1 + e2 + e3);
            gates[r][0] = e0 * inv; gates[r][1] = e1 * inv;
            gates[r][2] = e2 * inv; gates[r][3] = e3 * inv;
        }
    }
    __syncthreads();

    for (int q = t; q < 8 * 128; q += 256) {
        int r = q >> 7, d = q & 127;
        float any = g_any[i0 + r];
        float f;
        if (any != 0.0f)
            f = gates[r][0] * x[r][d] + gates[r][1] * x[r][128 + d]
              + gates[r][2] * x[r][256 + d] + gates[r][3] * x[r][384 + d];
        else
            f = x[r][d];
        g_agg[(size_t)(i0 + r) * DD + d] = f;
    }
}

// ---------- graph-conv layer + output ----------
__global__ __launch_bounds__(128) void gc_kernel(
    const float* __restrict__ gcw, const float* __restrict__ gcb,
    const float* __restrict__ lwp, int l, float* __restrict__ out)
{
    __shared__ float a[8][DD];
    int i0 = blockIdx.x * 8, t = threadIdx.x;
    #pragma unroll
    for (int r = 0; r < 8; r++) a[r][t] = g_agg[(size_t)(i0 + r) * DD + t];
    __syncthreads();

    float acc[8];
    float b = gcb[t];
    #pragma unroll
    for (int r = 0; r < 8; r++) acc[r] = b;
    #pragma unroll 4
    for (int kk = 0; kk < DD; kk++) {
        float w = gcw[kk * DD + t];
        #pragma unroll
        for (int r = 0; r < 8; r++) acc[r] += a[r][kk] * w;
    }

    float w0 = lwp[0], w1 = lwp[1];
    float m = fmaxf(w0, w1);
    float e0 = expf(w0 - m), e1 = expf(w1 - m);
    float lw = ((l == 0) ? e0 : e1) / (e0 + e1);

    #pragma unroll
    for (int r = 0; r < 8; r++) {
        float v = fmaxf(acc[r], 0.0f);
        size_t o = (size_t)(i0 + r) * DD + t;
        g_E[o] = v;
        if (l == 0) out[o] = lw * v;
        else        out[o] += lw * v;
    }
}

extern "C" void kernel_launch(void* const* d_in, const int* in_sizes, int n_in,
                              void* d_out, int out_size)
{
    const float* adj  = (const float*)d_in[0];
    const float* emb  = (const float*)d_in[1];
    const float* gc_w = (const float*)d_in[2];
    const float* gc_b = (const float*)d_in[3];
    const float* wq   = (const float*)d_in[4];
    const float* bq   = (const float*)d_in[5];
    const float* wk   = (const float*)d_in[6];
    const float* bk   = (const float*)d_in[7];
    const float* wv   = (const float*)d_in[8];
    const float* bv   = (const float*)d_in[9];
    const float* g1w  = (const float*)d_in[10];
    const float* g1b  = (const float*)d_in[11];
    const float* g2w  = (const float*)d_in[12];
    const float* g2b  = (const float*)d_in[13];
    const float* lw   = (const float*)d_in[14];
    float* out = (float*)d_out;

    const int simqk_smem  = 4 * 128 * 136 * 2;                 // 139264
    const int region_smem = 2 * 4 * 128 * 72 * 2 + 2 * 8192;   // 163840
    cudaFuncSetAttribute(simqk_mma, cudaFuncAttributeMaxDynamicSharedMemorySize, simqk_smem);
    cudaFuncSetAttribute(region_mma, cudaFuncAttributeMaxDynamicSharedMemorySize, region_smem);

    init_kernel<<<(NN * DD) / 256, 256>>>(emb);
    adjbits_kernel<<<(NN * NN / 32) / 256, 256>>>(adj);
    any_kernel<<<NN * 32 / 256, 256>>>();

    for (int l = 0; l < 2; l++) {
        norm_kernel<<<NN * 32 / 256, 256>>>();
        qkv_kernel<<<NN / 8, 128>>>(wq, bq, wk, bk, wv, bv);
        transpose_split_kernel<<<dim3(NN / 32, DD / 32), 256>>>();
        simqk_mma<<<dim3(64, 64), 256, simqk_smem>>>(0);
        simqk_mma<<<dim3(64, 64), 256, simqk_smem>>>(1);
        zero_flags_kernel<<<(3 * 64 * 128) / 256, 256>>>();
        classify_kernel<<<NN, 256>>>();
        region_mma<<<3 * (NN / 128), 256, region_smem>>>();
        gate_kernel<<<NN / 8, 256>>>(g1w, g1b, g2w, g2b);
        gc_kernel<<<NN / 8, 128>>>(gc_w + (size_t)l * DD * DD, gc_b + (size_t)l * DD,
                                   lw, l, out);
    }
}

// round 17
// speedup vs baseline: 1.3511x; 1.0711x over previous
#include <cuda_runtime.h>
#include <cuda_bf16.h>
#include <math.h>
#include <stdint.h>

#define NN 8192
#define DD 128
#define ALPHAC 0.7f
#define BETAC  0.3f
#define LAMC   0.1f
#define SIMWIN 1e-4f

static __device__ float g_E[NN * DD];
static __device__ float g_V[NN * DD];
static __device__ float g_invnorm[NN];
static __device__ float g_invp[NN];
static __device__ float g_invn[NN];
static __device__ float g_any[NN];
static __device__ float g_SIM[(size_t)NN * NN];                // sim (fp32)
static __device__ __nv_bfloat16 g_Pb[(size_t)NN * NN];         // attn scores (bf16)
static __device__ unsigned char g_code[(size_t)NN * NN];       // region code 0..3
static __device__ __nv_bfloat16 g_Phi[(size_t)NN * NN];        // softmax probs (bf16)
static __device__ unsigned int g_adjbits[NN * NN / 32];
static __device__ int g_flags[3 * 64 * 128];                   // [type][iblock][jchunk]
static __device__ __nv_bfloat16 g_Ehi[NN * DD], g_Elo[NN * DD];
static __device__ __nv_bfloat16 g_Qhi[NN * DD];
static __device__ __nv_bfloat16 g_Khi[NN * DD];
static __device__ __nv_bfloat16 g_Ethi[DD * NN], g_Etlo[DD * NN];
static __device__ __nv_bfloat16 g_Vthi[DD * NN], g_Vtlo[DD * NN];
static __device__ float g_pos[NN * DD];
static __device__ float g_neg[NN * DD];
static __device__ float g_bnd[NN * DD];
static __device__ float g_agg[NN * DD];

// ---------- baseline-PTX helpers ----------
__device__ __forceinline__ uint32_t smem_u32(const void* p) {
    uint32_t a;
    asm("{ .reg .u64 t; cvta.to.shared.u64 t, %1; cvt.u32.u64 %0, t; }" : "=r"(a) : "l"(p));
    return a;
}
__device__ __forceinline__ void ldsm4(uint32_t& r0, uint32_t& r1, uint32_t& r2, uint32_t& r3,
                                      uint32_t addr) {
    asm volatile("ldmatrix.sync.aligned.m8n8.x4.shared.b16 {%0,%1,%2,%3}, [%4];"
                 : "=r"(r0), "=r"(r1), "=r"(r2), "=r"(r3) : "r"(addr));
}
__device__ __forceinline__ void mma16816(float* c, uint32_t a0, uint32_t a1, uint32_t a2,
                                         uint32_t a3, uint32_t b0, uint32_t b1) {
    asm volatile(
        "mma.sync.aligned.m16n8k16.row.col.f32.bf16.bf16.f32 "
        "{%0,%1,%2,%3},{%4,%5,%6,%7},{%8,%9},{%0,%1,%2,%3};"
        : "+f"(c[0]), "+f"(c[1]), "+f"(c[2]), "+f"(c[3])
        : "r"(a0), "r"(a1), "r"(a2), "r"(a3), "r"(b0), "r"(b1));
}
__device__ __forceinline__ void cpa16(uint32_t saddr, const void* g) {
    asm volatile("cp.async.ca.shared.global [%0], [%1], 16;" :: "r"(saddr), "l"(g));
}
#define CP_COMMIT() asm volatile("cp.async.commit_group;" ::: "memory")
#define CP_WAIT0()  asm volatile("cp.async.wait_group 0;" ::: "memory")
#define CP_WAIT1()  asm volatile("cp.async.wait_group 1;" ::: "memory")

// ---------- small prep ----------
__global__ void init_kernel(const float* __restrict__ emb) {
    int idx = blockIdx.x * 256 + threadIdx.x;
    g_E[idx] = emb[idx];
}
__global__ void adjbits_kernel(const float* __restrict__ adj) {
    int w = blockIdx.x * 256 + threadIdx.x;
    size_t base = (size_t)w * 32;
    unsigned int bits = 0;
    #pragma unroll 8
    for (int b = 0; b < 32; b++) bits |= (adj[base + b] != 0.0f) ? (1u << b) : 0u;
    g_adjbits[w] = bits;
}
__global__ void any_kernel() {
    int i = (blockIdx.x * blockDim.x + threadIdx.x) >> 5;
    if (i >= NN) return;
    int lane = threadIdx.x & 31;
    unsigned int v = 0;
    #pragma unroll
    for (int w = 0; w < 8; w++) v |= g_adjbits[i * 256 + lane + w * 32];
    v = __any_sync(0xFFFFFFFFu, v != 0);
    if (lane == 0) g_any[i] = v ? 1.0f : 0.0f;
}
__global__ void zero_flags_kernel() {
    g_flags[blockIdx.x * 256 + threadIdx.x] = 0;
}
// norm + E hi/lo split (one warp per row)
__global__ void norm_kernel() {
    int gw = (blockIdx.x * blockDim.x + threadIdx.x) >> 5;
    if (gw >= NN) return;
    int lane = threadIdx.x & 31;
    size_t o = (size_t)gw * DD + lane * 4;
    float4 v = *(const float4*)(g_E + o);
    float s = v.x * v.x + v.y * v.y + v.z * v.z + v.w * v.w;
    #pragma unroll
    for (int of = 16; of > 0; of >>= 1) s += __shfl_xor_sync(0xFFFFFFFFu, s, of);
    if (lane == 0) g_invnorm[gw] = 1.0f / fmaxf(sqrtf(s), 1e-8f);
    __nv_bfloat16 hx = __float2bfloat16(v.x), hy = __float2bfloat16(v.y);
    __nv_bfloat16 hz = __float2bfloat16(v.z), hw = __float2bfloat16(v.w);
    *(__nv_bfloat162*)(g_Ehi + o)     = __halves2bfloat162(hx, hy);
    *(__nv_bfloat162*)(g_Ehi + o + 2) = __halves2bfloat162(hz, hw);
    *(__nv_bfloat162*)(g_Elo + o) = __halves2bfloat162(
        __float2bfloat16(v.x - __bfloat162float(hx)), __float2bfloat16(v.y - __bfloat162float(hy)));
    *(__nv_bfloat162*)(g_Elo + o + 2) = __halves2bfloat162(
        __float2bfloat16(v.z - __bfloat162float(hz)), __float2bfloat16(v.w - __bfloat162float(hw)));
}

// QKV + direct bf16 writes
__global__ __launch_bounds__(128) void qkv_kernel(
    const float* __restrict__ wq, const float* __restrict__ bq,
    const float* __restrict__ wk, const float* __restrict__ bk,
    const float* __restrict__ wv, const float* __restrict__ bv)
{
    __shared__ float e[8][DD];
    int i0 = blockIdx.x * 8, t = threadIdx.x;
    #pragma unroll
    for (int r = 0; r < 8; r++) e[r][t] = g_E[(size_t)(i0 + r) * DD + t];
    __syncthreads();
    float q[8], k[8], v[8];
    float bqv = bq[t], bkv = bk[t], bvv = bv[t];
    #pragma unroll
    for (int r = 0; r < 8; r++) { q[r] = bqv; k[r] = bkv; v[r] = bvv; }
    #pragma unroll 4
    for (int kk = 0; kk < DD; kk++) {
        float a = wq[kk * DD + t], b = wk[kk * DD + t], c = wv[kk * DD + t];
        #pragma unroll
        for (int r = 0; r < 8; r++) {
            float x = e[r][kk];
            q[r] += x * a; k[r] += x * b; v[r] += x * c;
        }
    }
    #pragma unroll
    for (int r = 0; r < 8; r++) {
        size_t o = (size_t)(i0 + r) * DD + t;
        g_Qhi[o] = __float2bfloat16(q[r]);
        g_Khi[o] = __float2bfloat16(k[r]);
        g_V[o] = v[r];
    }
}

__global__ __launch_bounds__(256) void transpose_split_kernel() {
    __shared__ float te[32][33], tv[32][33];
    int jb = blockIdx.x * 32, db = blockIdx.y * 32;
    int tx = threadIdx.x & 31, ty = threadIdx.x >> 5;
    #pragma unroll
    for (int r = 0; r < 32; r += 8) {
        te[ty + r][tx] = g_E[(size_t)(jb + ty + r) * DD + db + tx];
        tv[ty + r][tx] = g_V[(size_t)(jb + ty + r) * DD + db + tx];
    }
    __syncthreads();
    #pragma unroll
    for (int r = 0; r < 32; r += 8) {
        size_t o = (size_t)(db + ty + r) * NN + jb + tx;
        float e = te[tx][ty + r];
        __nv_bfloat16 h = __float2bfloat16(e);
        g_Ethi[o] = h; g_Etlo[o] = __float2bfloat16(e - __bfloat162float(h));
        float v = tv[tx][ty + r];
        h = __float2bfloat16(v);
        g_Vthi[o] = h; g_Vtlo[o] = __float2bfloat16(v - __bfloat162float(h));
    }
}

// ---------- NT GEMM via mma.sync ----------
// mode0: SIM = (E E^T)*invn_i*invn_j — A0·(B0,B1) merged + A1·B0 (3-pass), fp32 out
// mode1: P = (Q K^T)/sqrt(D) — single pass A0·B0, bf16 out
__global__ __launch_bounds__(256) void simqk_mma(int mode) {
    extern __shared__ char smem[];
    const int STR = 136;
    const int PLH = 128 * STR;
    __nv_bfloat16* sm = (__nv_bfloat16*)smem;
    const __nv_bfloat16* gA0 = (mode == 0) ? g_Ehi : g_Qhi;
    const __nv_bfloat16* gB0 = (mode == 0) ? g_Ehi : g_Khi;
    int tid = threadIdx.x;
    int m0 = blockIdx.y * 128, n0 = blockIdx.x * 128;

    for (int idx = tid; idx < 128 * 16; idx += 256) {
        int row = idx >> 4, cg = (idx & 15) * 8;
        size_t gm = (size_t)(m0 + row) * DD + cg;
        size_t gn = (size_t)(n0 + row) * DD + cg;
        int so = row * STR + cg;
        *(uint4*)(sm + 0 * PLH + so) = *(const uint4*)(gA0 + gm);
        *(uint4*)(sm + 2 * PLH + so) = *(const uint4*)(gB0 + gn);
        if (mode == 0) {
            *(uint4*)(sm + 1 * PLH + so) = *(const uint4*)(g_Elo + gm);
            *(uint4*)(sm + 3 * PLH + so) = *(const uint4*)(g_Elo + gn);
        }
    }
    __syncthreads();

    int wid = tid >> 5, lane = tid & 31;
    int wm = wid & 3, wn = wid >> 2;
    uint32_t sb = smem_u32(smem);
    float acc[2][8][4];
    #pragma unroll
    for (int i = 0; i < 2; i++)
        #pragma unroll
        for (int j = 0; j < 8; j++)
            #pragma unroll
            for (int q = 0; q < 4; q++) acc[i][j][q] = 0.0f;

    int a_row = (lane & 15), a_kh = (lane >> 4) * 8;
    int b_row = (lane >> 4) * 8 + (lane & 7), b_kh = ((lane >> 3) & 1) * 8;

    if (mode == 0) {
        #pragma unroll
        for (int ks = 0; ks < 8; ks++) {
            int k0 = ks * 16;
            uint32_t a[2][4];
            #pragma unroll
            for (int mt = 0; mt < 2; mt++) {
                int row = wm * 32 + mt * 16 + a_row;
                ldsm4(a[mt][0], a[mt][1], a[mt][2], a[mt][3],
                      sb + (uint32_t)(0 * PLH + row * STR + k0 + a_kh) * 2);
            }
            uint32_t b0[8][2], b1[8][2];
            #pragma unroll
            for (int np = 0; np < 4; np++) {
                int row = wn * 64 + np * 16 + b_row;
                ldsm4(b0[np * 2][0], b0[np * 2][1], b0[np * 2 + 1][0], b0[np * 2 + 1][1],
                      sb + (uint32_t)(2 * PLH + row * STR + k0 + b_kh) * 2);
                ldsm4(b1[np * 2][0], b1[np * 2][1], b1[np * 2 + 1][0], b1[np * 2 + 1][1],
                      sb + (uint32_t)(3 * PLH + row * STR + k0 + b_kh) * 2);
            }
            #pragma unroll
            for (int mt = 0; mt < 2; mt++)
                #pragma unroll
                for (int nt = 0; nt < 8; nt++) {
                    mma16816(acc[mt][nt], a[mt][0], a[mt][1], a[mt][2], a[mt][3],
                             b0[nt][0], b0[nt][1]);
                    mma16816(acc[mt][nt], a[mt][0], a[mt][1], a[mt][2], a[mt][3],
                             b1[nt][0], b1[nt][1]);
                }
        }
        #pragma unroll
        for (int ks = 0; ks < 8; ks++) {
            int k0 = ks * 16;
            uint32_t a[2][4];
            #pragma unroll
            for (int mt = 0; mt < 2; mt++) {
                int row = wm * 32 + mt * 16 + a_row;
                ldsm4(a[mt][0], a[mt][1], a[mt][2], a[mt][3],
                      sb + (uint32_t)(1 * PLH + row * STR + k0 + a_kh) * 2);
            }
            uint32_t b0[8][2];
            #pragma unroll
            for (int np = 0; np < 4; np++) {
                int row = wn * 64 + np * 16 + b_row;
                ldsm4(b0[np * 2][0], b0[np * 2][1], b0[np * 2 + 1][0], b0[np * 2 + 1][1],
                      sb + (uint32_t)(2 * PLH + row * STR + k0 + b_kh) * 2);
            }
            #pragma unroll
            for (int mt = 0; mt < 2; mt++)
                #pragma unroll
                for (int nt = 0; nt < 8; nt++)
                    mma16816(acc[mt][nt], a[mt][0], a[mt][1], a[mt][2], a[mt][3],
                             b0[nt][0], b0[nt][1]);
        }
    } else {
        #pragma unroll
        for (int ks = 0; ks < 8; ks++) {
            int k0 = ks * 16;
            uint32_t a[2][4];
            #pragma unroll
            for (int mt = 0; mt < 2; mt++) {
                int row = wm * 32 + mt * 16 + a_row;
                ldsm4(a[mt][0], a[mt][1], a[mt][2], a[mt][3],
                      sb + (uint32_t)(0 * PLH + row * STR + k0 + a_kh) * 2);
            }
            uint32_t b0[8][2];
            #pragma unroll
            for (int np = 0; np < 4; np++) {
                int row = wn * 64 + np * 16 + b_row;
                ldsm4(b0[np * 2][0], b0[np * 2][1], b0[np * 2 + 1][0], b0[np * 2 + 1][1],
                      sb + (uint32_t)(2 * PLH + row * STR + k0 + b_kh) * 2);
            }
            #pragma unroll
            for (int mt = 0; mt < 2; mt++)
                #pragma unroll
                for (int nt = 0; nt < 8; nt++)
                    mma16816(acc[mt][nt], a[mt][0], a[mt][1], a[mt][2], a[mt][3],
                             b0[nt][0], b0[nt][1]);
        }
    }

    const float ISD = 0.08838834764831845f;
    int g = lane >> 2, t = lane & 3;
    #pragma unroll
    for (int mt = 0; mt < 2; mt++) {
        int mrow = m0 + wm * 32 + mt * 16 + g;
        #pragma unroll
        for (int nt = 0; nt < 8; nt++) {
            int nc = n0 + wn * 64 + nt * 8 + t * 2;
            float* c = acc[mt][nt];
            if (mode == 0) {
                float sa0 = g_invnorm[mrow], sa1 = g_invnorm[mrow + 8];
                float sb0 = g_invnorm[nc], sb1 = g_invnorm[nc + 1];
                float2 w0 = { c[0] * sa0 * sb0, c[1] * sa0 * sb1 };
                float2 w1 = { c[2] * sa1 * sb0, c[3] * sa1 * sb1 };
                *(float2*)(g_SIM + (size_t)mrow * NN + nc) = w0;
                *(float2*)(g_SIM + (size_t)(mrow + 8) * NN + nc) = w1;
            } else {
                *(__nv_bfloat162*)(g_Pb + (size_t)mrow * NN + nc) =
                    __halves2bfloat162(__float2bfloat16(c[0] * ISD),
                                       __float2bfloat16(c[1] * ISD));
                *(__nv_bfloat162*)(g_Pb + (size_t)(mrow + 8) * NN + nc) =
                    __halves2bfloat162(__float2bfloat16(c[2] * ISD),
                                       __float2bfloat16(c[3] * ISD));
            }
        }
    }
}

// ---------- classify + masked softmax + chunk occupancy flags (vectorized) ----------
__device__ __forceinline__ float blk_sum(float v, float* buf) {
    int t = threadIdx.x;
    buf[t] = v; __syncthreads();
    #pragma unroll
    for (int s = 128; s > 0; s >>= 1) { if (t < s) buf[t] += buf[t + s]; __syncthreads(); }
    float r = buf[0]; __syncthreads();
    return r;
}
__device__ __forceinline__ float blk_max(float v, float* buf) {
    int t = threadIdx.x;
    buf[t] = v; __syncthreads();
    #pragma unroll
    for (int s = 128; s > 0; s >>= 1) { if (t < s) buf[t] = fmaxf(buf[t], buf[t + s]); __syncthreads(); }
    float r = buf[0]; __syncthreads();
    return r;
}

__global__ __launch_bounds__(256) void classify_kernel() {
    __shared__ float s2s[NN];
    __shared__ unsigned char cds[NN];
    __shared__ float erow[DD];
    __shared__ float rbuf[256];
    __shared__ unsigned char fl[3][128];
    int i = blockIdx.x, tid = threadIdx.x;
    size_t base = (size_t)i * NN;
    if (tid < DD) erow[tid] = g_E[(size_t)i * DD + tid];
    if (tid < 128) { fl[0][tid] = 0; fl[1][tid] = 0; fl[2][tid] = 0; }
    __syncthreads();
    float inv_i = g_invnorm[i];

    float cp = 0.f, cn = 0.f, mx = -INFINITY;
    for (int j = tid * 4; j < NN; j += 1024) {
        unsigned int w = g_adjbits[i * 256 + (j >> 5)];
        float4 sim4 = *(const float4*)(g_SIM + base + j);
        __nv_bfloat162 p01 = *(const __nv_bfloat162*)(g_Pb + base + j);
        __nv_bfloat162 p23 = *(const __nv_bfloat162*)(g_Pb + base + j + 2);
        float sims[4] = { sim4.x, sim4.y, sim4.z, sim4.w };
        float ss[4] = { __bfloat162float(__low2bfloat16(p01)),
                        __bfloat162float(__high2bfloat16(p01)),
                        __bfloat162float(__low2bfloat16(p23)),
                        __bfloat162float(__high2bfloat16(p23)) };
        int chunk = j >> 6;
        uchar4 k4;
        unsigned char* kp = (unsigned char*)&k4;
        #pragma unroll
        for (int e = 0; e < 4; e++) {
            int a = (w >> ((j + e) & 31)) & 1;
            int c = 0;
            if (a) {
                float sim = sims[e];
                if (fabsf(sim - ALPHAC) < SIMWIN || fabsf(sim - BETAC) < SIMWIN) {
                    const float* ej = g_E + (size_t)(j + e) * DD;
                    float dot = 0.f;
                    #pragma unroll 4
                    for (int d = 0; d < DD; d++) dot += erow[d] * ej[d];
                    sim = dot * inv_i * g_invnorm[j + e];
                }
                c = (sim >= ALPHAC) ? 1 : ((sim <= BETAC) ? 2 : 3);
                fl[c - 1][chunk] = 1;
                cp += (c == 1) ? 1.0f : 0.0f;
                cn += (c == 2) ? 1.0f : 0.0f;
                if (c == 3) mx = fmaxf(mx, ss[e]);
            }
            kp[e] = (unsigned char)c;
            cds[j + e] = (unsigned char)c;
            s2s[j + e] = ss[e];
        }
        *(uchar4*)(g_code + base + j) = k4;
    }
    cp = blk_sum(cp, rbuf);
    cn = blk_sum(cn, rbuf);
    mx = blk_max(mx, rbuf);
    if (mx == -INFINITY) mx = 0.0f;

    float s = 0.f;
    for (int j = tid * 2; j < NN; j += 512) {
        float e0 = (cds[j] == 3) ? expf(s2s[j] - mx) : 0.0f;
        float e1 = (cds[j + 1] == 3) ? expf(s2s[j + 1] - mx) : 0.0f;
        s2s[j] = e0; s2s[j + 1] = e1;
        s += e0 + e1;
    }
    s = blk_sum(s, rbuf);
    float inv = 1.0f / fmaxf(s, 1e-30f);
    for (int j = tid * 2; j < NN; j += 512) {
        float p0 = s2s[j] * inv, p1 = s2s[j + 1] * inv;
        *(__nv_bfloat162*)(g_Phi + base + j) =
            __halves2bfloat162(__float2bfloat16(p0), __float2bfloat16(p1));
    }
    int ib = i >> 7;
    if (tid < 128) {
        if (fl[0][tid]) g_flags[0 * 8192 + ib * 128 + tid] = 1;
        if (fl[1][tid]) g_flags[1 * 8192 + ib * 128 + tid] = 1;
        if (fl[2][tid]) g_flags[2 * 8192 + ib * 128 + tid] = 1;
    }
    if (tid == 0) {
        g_invp[i] = 1.0f / fmaxf(cp, 1.0f);
        g_invn[i] = LAMC / fmaxf(cn, 1.0f);
    }
}

// ---------- region GEMMs: chunk skipping + code->mask expansion ----------
// type0 pos: mask(code==1)·(Ethi,Etlo) 2p; type1 neg: mask(code==2)·Ethi 1p;
// type2 bnd: Phi·(Vthi,Vtlo) 2p (Plo dropped; weights bf16).
// Planes: 0=A, 2=B0, 3=B1. Pass p: A=plane0, B=(p==0?plane2:plane3).
__global__ __launch_bounds__(256) void region_mma() {
    extern __shared__ char smem[];
    __shared__ int lst[128];
    __shared__ int nch;
    __shared__ unsigned char fl[128];
    const int STR = 72;
    const int PLB = 128 * STR * 2;
    const int STAGE = 4 * PLB;
    const int CODE0 = 2 * STAGE;
    int tid = threadIdx.x;
    int type = blockIdx.x % 3;
    int ib = blockIdx.x / 3;
    int i0 = ib * 128;
    uint32_t sb = smem_u32(smem);

    if (tid < 128) fl[tid] = (unsigned char)g_flags[type * 8192 + ib * 128 + tid];
    __syncthreads();
    if (tid == 0) {
        int n = 0;
        for (int c = 0; c < 128; c++) if (fl[c]) lst[n++] = c;
        nch = n;
    }
    __syncthreads();
    int NCH = nch;

    const __nv_bfloat16* B0 = (type == 2) ? g_Vthi : g_Ethi;
    const __nv_bfloat16* B1 = (type == 2) ? g_Vtlo : g_Etlo;
    int npass = (type == 1) ? 1 : 2;
    unsigned char target = (type == 0) ? 1 : 2;

    int wid = tid >> 5, lane = tid & 31;
    int wm = wid & 3, wn = wid >> 2;
    float acc[2][8][4];
    #pragma unroll
    for (int i = 0; i < 2; i++)
        #pragma unroll
        for (int j = 0; j < 8; j++)
            #pragma unroll
            for (int q = 0; q < 4; q++) acc[i][j][q] = 0.0f;

    int a_row = (lane & 15), a_kh = (lane >> 4) * 8;
    int b_row = (lane >> 4) * 8 + (lane & 7), b_kh = ((lane >> 3) & 1) * 8;

    auto load_chunk = [&](int s, int chunkIdx) {
        int j0 = chunkIdx * 64;
        uint32_t st = sb + (uint32_t)(s * STAGE);
        if (type == 2) {
            for (int idx = tid; idx < 1024; idx += 256) {
                int row = idx >> 3, cg = (idx & 7) * 8;
                uint32_t so = (uint32_t)(row * STR + cg) * 2;
                cpa16(st + 0 * PLB + so, g_Phi + (size_t)(i0 + row) * NN + j0 + cg);
                cpa16(st + 2 * PLB + so, B0 + (size_t)row * NN + j0 + cg);
                cpa16(st + 3 * PLB + so, B1 + (size_t)row * NN + j0 + cg);
            }
        } else {
            uint32_t cst = sb + (uint32_t)(CODE0 + s * 8192);
            for (int idx = tid; idx < 512; idx += 256) {
                int row = idx >> 2, cg = (idx & 3) * 16;
                cpa16(cst + (uint32_t)(row * 64 + cg),
                      g_code + (size_t)(i0 + row) * NN + j0 + cg);
            }
            for (int idx = tid; idx < 1024; idx += 256) {
                int row = idx >> 3, cg = (idx & 7) * 8;
                uint32_t so = (uint32_t)(row * STR + cg) * 2;
                cpa16(st + 2 * PLB + so, B0 + (size_t)row * NN + j0 + cg);
                if (type == 0)
                    cpa16(st + 3 * PLB + so, B1 + (size_t)row * NN + j0 + cg);
            }
        }
    };

    if (NCH > 0) {
        load_chunk(0, lst[0]);
        CP_COMMIT();
        for (int ci = 0; ci < NCH; ci++) {
            int s = ci & 1;
            if (ci + 1 < NCH) {
                load_chunk(s ^ 1, lst[ci + 1]);
                CP_COMMIT();
                CP_WAIT1();
            } else {
                CP_WAIT0();
            }
            __syncthreads();

            uint32_t st = sb + (uint32_t)(s * STAGE);
            if (type != 2) {
                const unsigned char* cs =
                    (const unsigned char*)smem + CODE0 + s * 8192 + (tid >> 1) * 64 + (tid & 1) * 32;
                __nv_bfloat16* dst =
                    (__nv_bfloat16*)(smem + s * STAGE) + (tid >> 1) * STR + (tid & 1) * 32;
                const __nv_bfloat16 one = __float2bfloat16(1.0f);
                const __nv_bfloat16 zero = __float2bfloat16(0.0f);
                #pragma unroll
                for (int c = 0; c < 32; c += 2) {
                    *(__nv_bfloat162*)(dst + c) = __halves2bfloat162(
                        (cs[c] == target) ? one : zero,
                        (cs[c + 1] == target) ? one : zero);
                }
                __syncthreads();
            }

            for (int p = 0; p < npass; p++) {
                uint32_t abase = st;                                   // plane 0
                uint32_t bbase = st + (uint32_t)((p == 0 ? 2 : 3) * PLB);
                #pragma unroll
                for (int ks = 0; ks < 4; ks++) {
                    int k0 = ks * 16;
                    uint32_t a[2][4];
                    #pragma unroll
                    for (int mt = 0; mt < 2; mt++) {
                        int row = wm * 32 + mt * 16 + a_row;
                        ldsm4(a[mt][0], a[mt][1], a[mt][2], a[mt][3],
                              abase + (uint32_t)(row * STR + k0 + a_kh) * 2);
                    }
                    uint32_t b[8][2];
                    #pragma unroll
                    for (int np = 0; np < 4; np++) {
                        int row = wn * 64 + np * 16 + b_row;
                        ldsm4(b[np * 2][0], b[np * 2][1], b[np * 2 + 1][0], b[np * 2 + 1][1],
                              bbase + (uint32_t)(row * STR + k0 + b_kh) * 2);
                    }
                    #pragma unroll
                    for (int mt = 0; mt < 2; mt++)
                        #pragma unroll
                        for (int nt = 0; nt < 8; nt++)
                            mma16816(acc[mt][nt], a[mt][0], a[mt][1], a[mt][2], a[mt][3],
                                     b[nt][0], b[nt][1]);
                }
            }
            __syncthreads();
        }
    }

    float* dst = (type == 0) ? g_pos : (type == 1) ? g_neg : g_bnd;
    int g = lane >> 2, t = lane & 3;
    #pragma unroll
    for (int mt = 0; mt < 2; mt++) {
        int i = i0 + wm * 32 + mt * 16 + g;
        float s0 = (type == 0) ? g_invp[i] : (type == 1) ? g_invn[i] : 1.0f;
        float s1 = (type == 0) ? g_invp[i + 8] : (type == 1) ? g_invn[i + 8] : 1.0f;
        #pragma unroll
        for (int nt = 0; nt < 8; nt++) {
            int d = wn * 64 + nt * 8 + t * 2;
            float* c = acc[mt][nt];
            float2 w0 = { c[0] * s0, c[1] * s0 };
            float2 w1 = { c[2] * s1, c[3] * s1 };
            *(float2*)(dst + (size_t)i * DD + d) = w0;
            *(float2*)(dst + (size_t)(i + 8) * DD + d) = w1;
        }
    }
}

// ---------- gating MLP + fusion ----------
__global__ __launch_bounds__(256) void gate_kernel(
    const float* __restrict__ g1w, const float* __restrict__ g1b,
    const float* __restrict__ g2w, const float* __restrict__ g2b)
{
    __shared__ float x[8][512];
    __shared__ float h[8][257];
    __shared__ float gates[8][4];
    int i0 = blockIdx.x * 8, t = threadIdx.x;

    for (int q = t; q < 8 * 128; q += 256) {
        int r = q >> 7, d = q & 127;
        size_t o = (size_t)(i0 + r) * DD + d;
        x[r][d]       = g_E[o];
        x[r][128 + d] = g_pos[o];
        x[r][256 + d] = g_bnd[o];
        x[r][384 + d] = g_neg[o];
    }
    __syncthreads();

    float acc[8];
    float bb = g1b[t];
    #pragma unroll
    for (int r = 0; r < 8; r++) acc[r] = bb;
    #pragma unroll 4
    for (int kk = 0; kk < 512; kk++) {
        float w = g1w[kk * 256 + t];
        #pragma unroll
        for (int r = 0; r < 8; r++) acc[r] += x[r][kk] * w;
    }
    #pragma unroll
    for (int r = 0; r < 8; r++) h[r][t] = fmaxf(acc[r], 0.0f);
    __syncthreads();

    int wid = t >> 5, lane = t & 31;
    {
        int r = wid;
        float l0 = 0, l1 = 0, l2 = 0, l3 = 0;
        for (int kk = lane; kk < 256; kk += 32) {
            float hv = h[r][kk];
            l0 += hv * g2w[kk * 4 + 0];
            l1 += hv * g2w[kk * 4 + 1];
            l2 += hv * g2w[kk * 4 + 2];
            l3 += hv * g2w[kk * 4 + 3];
        }
        #pragma unroll
        for (int o = 16; o > 0; o >>= 1) {
            l0 += __shfl_xor_sync(0xFFFFFFFFu, l0, o);
            l1 += __shfl_xor_sync(0xFFFFFFFFu, l1, o);
            l2 += __shfl_xor_sync(0xFFFFFFFFu, l2, o);
            l3 += __shfl_xor_sync(0xFFFFFFFFu, l3, o);
        }
        if (lane == 0) {
            l0 += g2b[0]; l1 += g2b[1]; l2 += g2b[2]; l3 += g2b[3];
            float m = fmaxf(fmaxf(l0, l1), fmaxf(l2, l3));
            float e0 = expf(l0 - m), e1 = expf(l1 - m), e2 = expf(l2 - m), e3 = expf(l3 - m);
            float inv = 1.0f / (e0 + e1 + e2 + e3);
            gates[r][0] = e0 * inv; gates[r][1] = e1 * inv;
            gates[r][2] = e2 * inv; gates[r][3] = e3 * inv;
        }
    }
    __syncthreads();

    for (int q = t; q < 8 * 128; q += 256) {
        int r = q >> 7, d = q & 127;
        float any = g_any[i0 + r];
        float f;
        if (any != 0.0f)
            f = gates[r][0] * x[r][d] + gates[r][1] * x[r][128 + d]
              + gates[r][2] * x[r][256 + d] + gates[r][3] * x[r][384 + d];
        else
            f = x[r][d];
        g_agg[(size_t)(i0 + r) * DD + d] = f;
    }
}

// ---------- graph-conv layer + output ----------
__global__ __launch_bounds__(128) void gc_kernel(
    const float* __restrict__ gcw, const float* __restrict__ gcb,
    const float* __restrict__ lwp, int l, float* __restrict__ out)
{
    __shared__ float a[8][DD];
    int i0 = blockIdx.x * 8, t = threadIdx.x;
    #pragma unroll
    for (int r = 0; r < 8; r++) a[r][t] = g_agg[(size_t)(i0 + r) * DD + t];
    __syncthreads();

    float acc[8];
    float b = gcb[t];
    #pragma unroll
    for (int r = 0; r < 8; r++) acc[r] = b;
    #pragma unroll 4
    for (int kk = 0; kk < DD; kk++) {
        float w = gcw[kk * DD + t];
        #pragma unroll
        for (int r = 0; r < 8; r++) acc[r] += a[r][kk] * w;
    }

    float w0 = lwp[0], w1 = lwp[1];
    float m = fmaxf(w0, w1);
    float e0 = expf(w0 - m), e1 = expf(w1 - m);
    float lw = ((l == 0) ? e0 : e1) / (e0 + e1);

    #pragma unroll
    for (int r = 0; r < 8; r++) {
        float v = fmaxf(acc[r], 0.0f);
        size_t o = (size_t)(i0 + r) * DD + t;
        g_E[o] = v;
        if (l == 0) out[o] = lw * v;
        else        out[o] += lw * v;
    }
}

extern "C" void kernel_launch(void* const* d_in, const int* in_sizes, int n_in,
                              void* d_out, int out_size)
{
    const float* adj  = (const float*)d_in[0];
    const float* emb  = (const float*)d_in[1];
    const float* gc_w = (const float*)d_in[2];
    const float* gc_b = (const float*)d_in[3];
    const float* wq   = (const float*)d_in[4];
    const float* bq   = (const float*)d_in[5];
    const float* wk   = (const float*)d_in[6];
    const float* bk   = (const float*)d_in[7];
    const float* wv   = (const float*)d_in[8];
    const float* bv   = (const float*)d_in[9];
    const float* g1w  = (const float*)d_in[10];
    const float* g1b  = (const float*)d_in[11];
    const float* g2w  = (const float*)d_in[12];
    const float* g2b  = (const float*)d_in[13];
    const float* lw   = (const float*)d_in[14];
    float* out = (float*)d_out;

    const int simqk_smem  = 4 * 128 * 136 * 2;                 // 139264
    const int region_smem = 2 * 4 * 128 * 72 * 2 + 2 * 8192;   // 163840
    cudaFuncSetAttribute(simqk_mma, cudaFuncAttributeMaxDynamicSharedMemorySize, simqk_smem);
    cudaFuncSetAttribute(region_mma, cudaFuncAttributeMaxDynamicSharedMemorySize, region_smem);

    init_kernel<<<(NN * DD) / 256, 256>>>(emb);
    adjbits_kernel<<<(NN * NN / 32) / 256, 256>>>(adj);
    any_kernel<<<NN * 32 / 256, 256>>>();

    for (int l = 0; l < 2; l++) {
        norm_kernel<<<NN * 32 / 256, 256>>>();
        qkv_kernel<<<NN / 8, 128>>>(wq, bq, wk, bk, wv, bv);
        transpose_split_kernel<<<dim3(NN / 32, DD / 32), 256>>>();
        simqk_mma<<<dim3(64, 64), 256, simqk_smem>>>(0);
        simqk_mma<<<dim3(64, 64), 256, simqk_smem>>>(1);
        zero_flags_kernel<<<(3 * 64 * 128) / 256, 256>>>();
        classify_kernel<<<NN, 256>>>();
        region_mma<<<3 * (NN / 128), 256, region_smem>>>();
        gate_kernel<<<NN / 8, 256>>>(g1w, g1b, g2w, g2b);
        gc_kernel<<<NN / 8, 128>>>(gc_w + (size_t)l * DD * DD, gc_b + (size_t)l * DD,
                                   lw, l, out);
    }
}